// round 3
// baseline (speedup 1.0000x reference)
#include <cuda_runtime.h>
#include <cuda_bf16.h>
#include <math.h>

// Problem constants
#define BB 4
#define NN 20000
#define DD 64
#define KK 256
#define HH 4
#define DHD 16
#define FF 256
#define LLAYERS 2
#define NSPLIT 40
#define CHUNK (NN / NSPLIT)      // 500
#define ROWTILES ((NN + 255) / 256)  // 79

#define ATTN_SMEM_FLOATS (16384 + 16384 + 4096 + 4096 + 64 + 64 + 64)  // 41152
#define ATTN_SMEM_BYTES (ATTN_SMEM_FLOATS * 4)                          // 164608
#define FFN_SMEM_FLOATS (16384 + 16384 + 256 + 64 + 64 + 64)            // 33216
#define FFN_SMEM_BYTES (FFN_SMEM_FLOATS * 4)                            // 132864

// Scratch (module-scope device arrays; no runtime allocation)
__device__ float g_x[BB * NN * DD];                 // activations  [B,N,D]
__device__ float g_part[NSPLIT * 2 * BB * KK * DD]; // split-N partials
__device__ float g_kvlow[2 * BB * KK * DD];         // reduced k_low / v_low
__device__ float g_k[BB * KK * DD];                 // k = k_low @ Wk
__device__ float g_v[BB * KK * DD];                 // v = v_low @ Wv

// ---------------------------------------------------------------------------
// x[b,n,d] = emb[n,d] * expr[b,n]
__global__ void embed_kernel(const float* __restrict__ expr,
                             const float* __restrict__ emb) {
    int idx = blockIdx.x * blockDim.x + threadIdx.x;  // row id over B*N
    if (idx >= BB * NN) return;
    int b = idx / NN, n = idx % NN;
    float e = expr[b * NN + n];
    const float4* er = (const float4*)&emb[(size_t)n * DD];
    float4* xo = (float4*)&g_x[(size_t)idx * DD];
#pragma unroll
    for (int i = 0; i < DD / 4; i++) {
        float4 v = er[i];
        v.x *= e; v.y *= e; v.z *= e; v.w *= e;
        xo[i] = v;
    }
}

// ---------------------------------------------------------------------------
// Split-N low-rank projection:
//   part[s,mat,b,k,d] = sum_{n in chunk s} P[n,k] * x[b,n,d]
// grid (NSPLIT, B, 2), 256 threads. Thread tile: 16 k x 4 d.
__global__ __launch_bounds__(256) void proj_kernel(const float* __restrict__ PK,
                                                   const float* __restrict__ PV) {
    int s = blockIdx.x, b = blockIdx.y, mat = blockIdx.z;
    const float* P = (mat == 0) ? PK : PV;
    __shared__ float sP[4][KK];
    __shared__ float sX[4][DD];
    int t = threadIdx.x;
    int tk = t & 15;       // k sub-tile
    int td = t >> 4;       // d sub-tile
    float acc[16][4];
#pragma unroll
    for (int i = 0; i < 16; i++)
#pragma unroll
        for (int j = 0; j < 4; j++) acc[i][j] = 0.f;

    int n0 = s * CHUNK;
    for (int n = n0; n < n0 + CHUNK; n += 4) {
        {   // stage 4 P rows (1024 floats = 256 float4)
            int r = t >> 6;
            int c = (t & 63) * 4;
            *(float4*)&sP[r][c] = *(const float4*)&P[(size_t)(n + r) * KK + c];
        }
        if (t < 64) {  // stage 4 x rows (256 floats = 64 float4)
            int r = t >> 4;
            int c = (t & 15) * 4;
            *(float4*)&sX[r][c] = *(const float4*)&g_x[((size_t)b * NN + n + r) * DD + c];
        }
        __syncthreads();
#pragma unroll
        for (int j = 0; j < 4; j++) {
            float4 xv = *(float4*)&sX[j][td * 4];
            float pk[16];
#pragma unroll
            for (int i = 0; i < 16; i += 4) {
                float4 pv = *(float4*)&sP[j][tk * 16 + i];
                pk[i] = pv.x; pk[i + 1] = pv.y; pk[i + 2] = pv.z; pk[i + 3] = pv.w;
            }
#pragma unroll
            for (int i = 0; i < 16; i++) {
                acc[i][0] += pk[i] * xv.x;
                acc[i][1] += pk[i] * xv.y;
                acc[i][2] += pk[i] * xv.z;
                acc[i][3] += pk[i] * xv.w;
            }
        }
        __syncthreads();
    }
    float* o = g_part + (((size_t)s * 2 + mat) * BB + b) * (KK * DD);
#pragma unroll
    for (int i = 0; i < 16; i++) {
        int k = tk * 16 + i;
        *(float4*)&o[k * DD + td * 4] =
            make_float4(acc[i][0], acc[i][1], acc[i][2], acc[i][3]);
    }
}

// ---------------------------------------------------------------------------
// kvlow[mat,b,k,d] = sum_s part[s,mat,b,k,d]    (deterministic reduction)
__global__ void reduce_kernel() {
    int idx = blockIdx.x * blockDim.x + threadIdx.x;  // [0, 2*B*K*D)
    if (idx >= 2 * BB * KK * DD) return;
    float sum = 0.f;
#pragma unroll 8
    for (int s = 0; s < NSPLIT; s++)
        sum += g_part[(size_t)s * (2 * BB * KK * DD) + idx];
    g_kvlow[idx] = sum;
}

// ---------------------------------------------------------------------------
// k[b,k,e] = sum_d kvlow[0,b,k,d] * Wk[d,e];  v likewise with Wv.
// grid (K/4, B, 2), 256 threads: 4 k-rows x 64 e.
__global__ void kvproj_kernel(const float* __restrict__ Wk,
                              const float* __restrict__ Wv) {
    int mat = blockIdx.z, b = blockIdx.y;
    const float* W = (mat == 0) ? Wk : Wv;
    __shared__ float sW[DD * DD];
    __shared__ float sL[4][DD];
    int t = threadIdx.x;
    for (int i = t * 4; i < DD * DD; i += 1024)
        *(float4*)&sW[i] = *(const float4*)&W[i];
    if (t < 64) {
        int r = t >> 4, c = (t & 15) * 4;
        int k = blockIdx.x * 4 + r;
        *(float4*)&sL[r][c] =
            *(const float4*)&g_kvlow[((size_t)mat * BB + b) * KK * DD + k * DD + c];
    }
    __syncthreads();
    int e = t & 63, kr = t >> 6;
    int k = blockIdx.x * 4 + kr;
    float sacc = 0.f;
#pragma unroll
    for (int d = 0; d < DD; d++) sacc += sL[kr][d] * sW[d * DD + e];
    float* out = (mat == 0) ? g_k : g_v;
    out[(size_t)b * KK * DD + k * DD + e] = sacc;
}

// ---------------------------------------------------------------------------
// Fused attention: q-proj, dots, softmax, o, Wo-proj, +bo, residual, LN1.
// In-place on g_x. grid (ROWTILES, B), 256 threads, thread = one row.
__global__ __launch_bounds__(256, 1) void attn_kernel(const float* __restrict__ Wq,
                                                      const float* __restrict__ Wo,
                                                      const float* __restrict__ bo,
                                                      const float* __restrict__ g1,
                                                      const float* __restrict__ be1) {
    extern __shared__ float sm[];
    float* sK = sm;                  // 16384
    float* sV = sK + KK * DD;        // 16384
    float* sWq = sV + KK * DD;       // 4096
    float* sWo = sWq + DD * DD;      // 4096
    float* sBo = sWo + DD * DD;      // 64
    float* sG = sBo + DD;            // 64
    float* sBe = sG + DD;            // 64
    int b = blockIdx.y;
    int t = threadIdx.x;

    const float* kb = g_k + (size_t)b * KK * DD;
    const float* vb = g_v + (size_t)b * KK * DD;
    for (int i = t * 4; i < KK * DD; i += 1024) {
        *(float4*)&sK[i] = *(const float4*)&kb[i];
        *(float4*)&sV[i] = *(const float4*)&vb[i];
    }
    for (int i = t * 4; i < DD * DD; i += 1024) {
        *(float4*)&sWq[i] = *(const float4*)&Wq[i];
        *(float4*)&sWo[i] = *(const float4*)&Wo[i];
    }
    if (t < 16) {
        *(float4*)&sBo[t * 4] = *(const float4*)&bo[t * 4];
        *(float4*)&sG[t * 4] = *(const float4*)&g1[t * 4];
        *(float4*)&sBe[t * 4] = *(const float4*)&be1[t * 4];
    }
    __syncthreads();

    int n = blockIdx.x * 256 + t;
    if (n >= NN) return;

    float* xp = g_x + ((size_t)b * NN + n) * DD;
    float xr[DD];
#pragma unroll
    for (int i = 0; i < DD; i += 4) {
        float4 v4 = *(const float4*)&xp[i];
        xr[i] = v4.x; xr[i + 1] = v4.y; xr[i + 2] = v4.z; xr[i + 3] = v4.w;
    }

    float ofull[DD];
#pragma unroll
    for (int h = 0; h < HH; h++) {
        // qh = xr @ Wq[:, h*16 : h*16+16]
        float qh[DHD];
#pragma unroll
        for (int j = 0; j < DHD; j++) qh[j] = 0.f;
#pragma unroll 4
        for (int d = 0; d < DD; d++) {
            float xd = xr[d];
            const float* wr = &sWq[d * DD + h * DHD];
#pragma unroll
            for (int j = 0; j < DHD; j += 4) {
                float4 w = *(float4*)&wr[j];
                qh[j] += xd * w.x; qh[j + 1] += xd * w.y;
                qh[j + 2] += xd * w.z; qh[j + 3] += xd * w.w;
            }
        }
        // streaming softmax (no max-subtraction: |dots| << 1 by construction)
        float oh[DHD];
#pragma unroll
        for (int j = 0; j < DHD; j++) oh[j] = 0.f;
        float l = 0.f;
#pragma unroll 2
        for (int k = 0; k < KK; k++) {
            const float* kr = &sK[k * DD + h * DHD];
            float s = 0.f;
#pragma unroll
            for (int j = 0; j < DHD; j += 4) {
                float4 w = *(float4*)&kr[j];
                s += qh[j] * w.x + qh[j + 1] * w.y + qh[j + 2] * w.z + qh[j + 3] * w.w;
            }
            float p = __expf(s * 0.25f);
            l += p;
            const float* vr = &sV[k * DD + h * DHD];
#pragma unroll
            for (int j = 0; j < DHD; j += 4) {
                float4 w = *(float4*)&vr[j];
                oh[j] += p * w.x; oh[j + 1] += p * w.y;
                oh[j + 2] += p * w.z; oh[j + 3] += p * w.w;
            }
        }
        float inv = 1.f / l;
#pragma unroll
        for (int j = 0; j < DHD; j++) ofull[h * DHD + j] = oh[j] * inv;
    }

    // xr += bo + ofull @ Wo   (residual folded in place)
#pragma unroll
    for (int e = 0; e < DD; e++) xr[e] += sBo[e];
#pragma unroll 4
    for (int d = 0; d < DD; d++) {
        float od = ofull[d];
        const float* wr = &sWo[d * DD];
#pragma unroll
        for (int e = 0; e < DD; e += 4) {
            float4 w = *(float4*)&wr[e];
            xr[e] += od * w.x; xr[e + 1] += od * w.y;
            xr[e + 2] += od * w.z; xr[e + 3] += od * w.w;
        }
    }

    // LayerNorm
    float m = 0.f;
#pragma unroll
    for (int d = 0; d < DD; d++) m += xr[d];
    m *= (1.f / DD);
    float var = 0.f;
#pragma unroll
    for (int d = 0; d < DD; d++) { float df = xr[d] - m; var += df * df; }
    var *= (1.f / DD);
    float inv = rsqrtf(var + 1e-5f);
#pragma unroll
    for (int i = 0; i < DD; i += 4) {
        float4 o4;
        o4.x = (xr[i] - m) * inv * sG[i] + sBe[i];
        o4.y = (xr[i + 1] - m) * inv * sG[i + 1] + sBe[i + 1];
        o4.z = (xr[i + 2] - m) * inv * sG[i + 2] + sBe[i + 2];
        o4.w = (xr[i + 3] - m) * inv * sG[i + 3] + sBe[i + 3];
        *(float4*)&xp[i] = o4;
    }
}

// ---------------------------------------------------------------------------
// Fused FFN: h = gelu_exact(x@W1+b1); f = h@W2+b2; LN2(f + x) -> xout
// grid (ROWTILES, B), 256 threads, thread = one row.
__global__ __launch_bounds__(256, 1) void ffn_kernel(const float* __restrict__ W1,
                                                     const float* __restrict__ b1,
                                                     const float* __restrict__ W2,
                                                     const float* __restrict__ b2,
                                                     const float* __restrict__ g2,
                                                     const float* __restrict__ be2,
                                                     float* __restrict__ xout) {
    extern __shared__ float sm[];
    float* sW1 = sm;                  // 16384  [D,F] natural layout
    float* sW2 = sW1 + DD * FF;       // 16384  [F,D]
    float* sB1 = sW2 + FF * DD;       // 256
    float* sB2 = sB1 + FF;            // 64
    float* sG = sB2 + DD;             // 64
    float* sBe = sG + DD;             // 64
    int b = blockIdx.y;
    int t = threadIdx.x;

    for (int i = t * 4; i < DD * FF; i += 1024) {
        *(float4*)&sW1[i] = *(const float4*)&W1[i];
        *(float4*)&sW2[i] = *(const float4*)&W2[i];
    }
    if (t < 64) *(float4*)&sB1[t * 4] = *(const float4*)&b1[t * 4];
    if (t < 16) {
        *(float4*)&sB2[t * 4] = *(const float4*)&b2[t * 4];
        *(float4*)&sG[t * 4] = *(const float4*)&g2[t * 4];
        *(float4*)&sBe[t * 4] = *(const float4*)&be2[t * 4];
    }
    __syncthreads();

    int n = blockIdx.x * 256 + t;
    if (n >= NN) return;

    const float* xp = g_x + ((size_t)b * NN + n) * DD;
    float xr[DD];
#pragma unroll
    for (int i = 0; i < DD; i += 4) {
        float4 v4 = *(const float4*)&xp[i];
        xr[i] = v4.x; xr[i + 1] = v4.y; xr[i + 2] = v4.z; xr[i + 3] = v4.w;
    }

    float facc[DD];
#pragma unroll
    for (int e = 0; e < DD; e++) facc[e] = 0.f;

    for (int f = 0; f < FF; f += 4) {
        float4 hv = *(float4*)&sB1[f];
#pragma unroll 4
        for (int d = 0; d < DD; d++) {
            float xd = xr[d];
            float4 w = *(float4*)&sW1[d * FF + f];
            hv.x += xd * w.x; hv.y += xd * w.y; hv.z += xd * w.z; hv.w += xd * w.w;
        }
        // exact GELU (matches jax approximate=False)
        float h0 = 0.5f * hv.x * (1.f + erff(hv.x * 0.70710678118654752f));
        float h1 = 0.5f * hv.y * (1.f + erff(hv.y * 0.70710678118654752f));
        float h2 = 0.5f * hv.z * (1.f + erff(hv.z * 0.70710678118654752f));
        float h3 = 0.5f * hv.w * (1.f + erff(hv.w * 0.70710678118654752f));
        const float* w20 = &sW2[(f + 0) * DD];
        const float* w21 = &sW2[(f + 1) * DD];
        const float* w22 = &sW2[(f + 2) * DD];
        const float* w23 = &sW2[(f + 3) * DD];
#pragma unroll
        for (int e = 0; e < DD; e += 4) {
            float4 a = *(float4*)&w20[e];
            float4 bq = *(float4*)&w21[e];
            float4 c = *(float4*)&w22[e];
            float4 dq = *(float4*)&w23[e];
            facc[e] += h0 * a.x + h1 * bq.x + h2 * c.x + h3 * dq.x;
            facc[e + 1] += h0 * a.y + h1 * bq.y + h2 * c.y + h3 * dq.y;
            facc[e + 2] += h0 * a.z + h1 * bq.z + h2 * c.z + h3 * dq.z;
            facc[e + 3] += h0 * a.w + h1 * bq.w + h2 * c.w + h3 * dq.w;
        }
    }

    // residual + bias, then LN
#pragma unroll
    for (int e = 0; e < DD; e++) xr[e] += facc[e] + sB2[e];

    float m = 0.f;
#pragma unroll
    for (int d = 0; d < DD; d++) m += xr[d];
    m *= (1.f / DD);
    float var = 0.f;
#pragma unroll
    for (int d = 0; d < DD; d++) { float df = xr[d] - m; var += df * df; }
    var *= (1.f / DD);
    float inv = rsqrtf(var + 1e-5f);
    float* op = xout + ((size_t)b * NN + n) * DD;
#pragma unroll
    for (int i = 0; i < DD; i += 4) {
        float4 o4;
        o4.x = (xr[i] - m) * inv * sG[i] + sBe[i];
        o4.y = (xr[i + 1] - m) * inv * sG[i + 1] + sBe[i + 1];
        o4.z = (xr[i + 2] - m) * inv * sG[i + 2] + sBe[i + 2];
        o4.w = (xr[i + 3] - m) * inv * sG[i + 3] + sBe[i + 3];
        *(float4*)&op[i] = o4;
    }
}

// ---------------------------------------------------------------------------
extern "C" void kernel_launch(void* const* d_in, const int* in_sizes, int n_in,
                              void* d_out, int out_size) {
    const float* expr = (const float*)d_in[0];
    const float* emb = (const float*)d_in[1];
    const float* Wq = (const float*)d_in[2];
    const float* Wk = (const float*)d_in[3];
    const float* Wv = (const float*)d_in[4];
    const float* projK = (const float*)d_in[5];
    const float* projV = (const float*)d_in[6];
    const float* Wo = (const float*)d_in[7];
    const float* bo = (const float*)d_in[8];
    const float* g1 = (const float*)d_in[9];
    const float* be1 = (const float*)d_in[10];
    const float* W1 = (const float*)d_in[11];
    const float* bf1 = (const float*)d_in[12];
    const float* W2 = (const float*)d_in[13];
    const float* bf2 = (const float*)d_in[14];
    const float* g2 = (const float*)d_in[15];
    const float* be2 = (const float*)d_in[16];
    float* out = (float*)d_out;

    void* xaddr = nullptr;
    cudaGetSymbolAddress(&xaddr, g_x);
    float* gx = (float*)xaddr;

    cudaFuncSetAttribute(attn_kernel, cudaFuncAttributeMaxDynamicSharedMemorySize,
                         ATTN_SMEM_BYTES);
    cudaFuncSetAttribute(ffn_kernel, cudaFuncAttributeMaxDynamicSharedMemorySize,
                         FFN_SMEM_BYTES);

    embed_kernel<<<(BB * NN + 255) / 256, 256>>>(expr, emb);

    for (int l = 0; l < LLAYERS; l++) {
        proj_kernel<<<dim3(NSPLIT, BB, 2), 256>>>(projK + (size_t)l * NN * KK,
                                                  projV + (size_t)l * NN * KK);
        reduce_kernel<<<(2 * BB * KK * DD) / 256, 256>>>();
        kvproj_kernel<<<dim3(KK / 4, BB, 2), 256>>>(Wk + l * DD * DD,
                                                    Wv + l * DD * DD);
        attn_kernel<<<dim3(ROWTILES, BB), 256, ATTN_SMEM_BYTES>>>(
            Wq + l * DD * DD, Wo + l * DD * DD, bo + l * DD, g1 + l * DD,
            be1 + l * DD);
        ffn_kernel<<<dim3(ROWTILES, BB), 256, FFN_SMEM_BYTES>>>(
            W1 + l * DD * FF, bf1 + l * FF, W2 + l * FF * DD, bf2 + l * DD,
            g2 + l * DD, be2 + l * DD, (l == LLAYERS - 1) ? out : gx);
    }
}

// round 5
// speedup vs baseline: 1.1911x; 1.1911x over previous
#include <cuda_runtime.h>
#include <cuda_bf16.h>
#include <math.h>

// Problem constants
#define BB 4
#define NN 20000
#define DD 64
#define KK 256
#define HH 4
#define DHD 16
#define FF 256
#define LLAYERS 2
#define NSPLIT 40
#define CHUNK (NN / NSPLIT)          // 500
#define ROWT ((NN + 127) / 128)      // 157

// attn smem: K half 8192 + V half 8192 + Wq 4096 + Wo 4096 + bo/g/be 192
#define ATTN_SMEM_FLOATS (8192 + 8192 + 4096 + 4096 + 64 + 64 + 64)   // 24768
#define ATTN_SMEM_BYTES (ATTN_SMEM_FLOATS * 4)                        // 99072
// ffn smem: W1 half 8192 + W2 half 8192 + b1 half 128 + b2/g/be 192
#define FFN_SMEM_FLOATS (8192 + 8192 + 128 + 64 + 64 + 64)            // 16704
#define FFN_SMEM_BYTES (FFN_SMEM_FLOATS * 4)                          // 66816

typedef unsigned long long u64;

__device__ __forceinline__ u64 pk2(float a, float b) {
    u64 r; asm("mov.b64 %0,{%1,%2};" : "=l"(r) : "f"(a), "f"(b)); return r;
}
__device__ __forceinline__ u64 bc2(float a) { return pk2(a, a); }
__device__ __forceinline__ float2 up2(u64 v) {
    float2 r; asm("mov.b64 {%0,%1},%2;" : "=f"(r.x), "=f"(r.y) : "l"(v)); return r;
}
__device__ __forceinline__ u64 f2fma(u64 a, u64 b, u64 c) {
    u64 d; asm("fma.rn.f32x2 %0,%1,%2,%3;" : "=l"(d) : "l"(a), "l"(b), "l"(c)); return d;
}
__device__ __forceinline__ u64 f2add(u64 a, u64 b) {
    u64 d; asm("add.rn.f32x2 %0,%1,%2;" : "=l"(d) : "l"(a), "l"(b)); return d;
}
__device__ __forceinline__ u64 f2mul(u64 a, u64 b) {
    u64 d; asm("mul.rn.f32x2 %0,%1,%2;" : "=l"(d) : "l"(a), "l"(b)); return d;
}

// Scratch (module-scope device arrays; no runtime allocation)
__device__ float g_x[BB * NN * DD];                 // activations  [B,N,D]
__device__ float g_part[NSPLIT * 2 * BB * KK * DD]; // split-N partials
__device__ float g_kvlow[2 * BB * KK * DD];         // reduced k_low / v_low
__device__ float g_k[BB * KK * DD];                 // k = k_low @ Wk
__device__ float g_v[BB * KK * DD];                 // v = v_low @ Wv

// ---------------------------------------------------------------------------
// x[b,n,d] = emb[n,d] * expr[b,n]
__global__ void embed_kernel(const float* __restrict__ expr,
                             const float* __restrict__ emb) {
    int idx = blockIdx.x * blockDim.x + threadIdx.x;
    if (idx >= BB * NN) return;
    int b = idx / NN, n = idx % NN;
    float e = expr[b * NN + n];
    const float4* er = (const float4*)&emb[(size_t)n * DD];
    float4* xo = (float4*)&g_x[(size_t)idx * DD];
#pragma unroll
    for (int i = 0; i < DD / 4; i++) {
        float4 v = er[i];
        v.x *= e; v.y *= e; v.z *= e; v.w *= e;
        xo[i] = v;
    }
}

// ---------------------------------------------------------------------------
// Split-N low-rank projection with f32x2 packed FMA:
//   part[s,mat,b,k,d] = sum_{n in chunk s} P[n,k] * x[b,n,d]
__global__ __launch_bounds__(256) void proj_kernel(const float* __restrict__ PK,
                                                   const float* __restrict__ PV) {
    int s = blockIdx.x, b = blockIdx.y, mat = blockIdx.z;
    const float* P = (mat == 0) ? PK : PV;
    __shared__ float sP[4][KK];
    __shared__ float sX[4][DD];
    int t = threadIdx.x;
    int tk = t & 15;       // k sub-tile (16 k-rows -> 8 packed pairs)
    int td = t >> 4;       // d sub-tile (4 d)
    u64 acc2[8][4];
#pragma unroll
    for (int i = 0; i < 8; i++)
#pragma unroll
        for (int j = 0; j < 4; j++) acc2[i][j] = 0ull;

    int n0 = s * CHUNK;
    for (int n = n0; n < n0 + CHUNK; n += 4) {
        {   // stage 4 P rows
            int r = t >> 6;
            int c = (t & 63) * 4;
            *(float4*)&sP[r][c] = *(const float4*)&P[(size_t)(n + r) * KK + c];
        }
        if (t < 64) {  // stage 4 x rows
            int r = t >> 4;
            int c = (t & 15) * 4;
            *(float4*)&sX[r][c] = *(const float4*)&g_x[((size_t)b * NN + n + r) * DD + c];
        }
        __syncthreads();
#pragma unroll
        for (int j = 0; j < 4; j++) {
            float4 xv = *(float4*)&sX[j][td * 4];
            u64 xb0 = bc2(xv.x), xb1 = bc2(xv.y), xb2 = bc2(xv.z), xb3 = bc2(xv.w);
            const ulonglong2* pp = (const ulonglong2*)&sP[j][tk * 16];
#pragma unroll
            for (int q = 0; q < 4; q++) {
                ulonglong2 pw = pp[q];
                acc2[2 * q][0] = f2fma(pw.x, xb0, acc2[2 * q][0]);
                acc2[2 * q][1] = f2fma(pw.x, xb1, acc2[2 * q][1]);
                acc2[2 * q][2] = f2fma(pw.x, xb2, acc2[2 * q][2]);
                acc2[2 * q][3] = f2fma(pw.x, xb3, acc2[2 * q][3]);
                acc2[2 * q + 1][0] = f2fma(pw.y, xb0, acc2[2 * q + 1][0]);
                acc2[2 * q + 1][1] = f2fma(pw.y, xb1, acc2[2 * q + 1][1]);
                acc2[2 * q + 1][2] = f2fma(pw.y, xb2, acc2[2 * q + 1][2]);
                acc2[2 * q + 1][3] = f2fma(pw.y, xb3, acc2[2 * q + 1][3]);
            }
        }
        __syncthreads();
    }
    float* o = g_part + (((size_t)s * 2 + mat) * BB + b) * (KK * DD);
#pragma unroll
    for (int ii = 0; ii < 8; ii++) {
        float2 u0 = up2(acc2[ii][0]), u1 = up2(acc2[ii][1]);
        float2 u2 = up2(acc2[ii][2]), u3 = up2(acc2[ii][3]);
        int k0 = tk * 16 + 2 * ii;
        *(float4*)&o[k0 * DD + td * 4] = make_float4(u0.x, u1.x, u2.x, u3.x);
        *(float4*)&o[(k0 + 1) * DD + td * 4] = make_float4(u0.y, u1.y, u2.y, u3.y);
    }
}

// ---------------------------------------------------------------------------
__global__ void reduce_kernel() {
    int idx = blockIdx.x * blockDim.x + threadIdx.x;
    if (idx >= 2 * BB * KK * DD) return;
    float sum = 0.f;
#pragma unroll 8
    for (int s = 0; s < NSPLIT; s++)
        sum += g_part[(size_t)s * (2 * BB * KK * DD) + idx];
    g_kvlow[idx] = sum;
}

// ---------------------------------------------------------------------------
__global__ void kvproj_kernel(const float* __restrict__ Wk,
                              const float* __restrict__ Wv) {
    int mat = blockIdx.z, b = blockIdx.y;
    const float* W = (mat == 0) ? Wk : Wv;
    __shared__ float sW[DD * DD];
    __shared__ float sL[4][DD];
    int t = threadIdx.x;
    for (int i = t * 4; i < DD * DD; i += 1024)
        *(float4*)&sW[i] = *(const float4*)&W[i];
    if (t < 64) {
        int r = t >> 4, c = (t & 15) * 4;
        int k = blockIdx.x * 4 + r;
        *(float4*)&sL[r][c] =
            *(const float4*)&g_kvlow[((size_t)mat * BB + b) * KK * DD + k * DD + c];
    }
    __syncthreads();
    int e = t & 63, kr = t >> 6;
    int k = blockIdx.x * 4 + kr;
    float sacc = 0.f;
#pragma unroll
    for (int d = 0; d < DD; d++) sacc += sL[kr][d] * sW[d * DD + e];
    float* out = (mat == 0) ? g_k : g_v;
    out[(size_t)b * KK * DD + k * DD + e] = sacc;
}

// ---------------------------------------------------------------------------
// LayerNorm epilogue on packed row, store fp32
__device__ __forceinline__ void ln_store(u64* xr2, const float* sG,
                                         const float* sBe, float* op) {
    float xs[DD];
#pragma unroll
    for (int jj = 0; jj < 32; jj++) {
        float2 v = up2(xr2[jj]);
        xs[2 * jj] = v.x; xs[2 * jj + 1] = v.y;
    }
    float m = 0.f;
#pragma unroll
    for (int d = 0; d < DD; d++) m += xs[d];
    m *= (1.f / DD);
    float var = 0.f;
#pragma unroll
    for (int d = 0; d < DD; d++) { float df = xs[d] - m; var += df * df; }
    var *= (1.f / DD);
    float inv = rsqrtf(var + 1e-5f);
#pragma unroll
    for (int i = 0; i < DD; i += 4) {
        float4 o4;
        o4.x = (xs[i] - m) * inv * sG[i] + sBe[i];
        o4.y = (xs[i + 1] - m) * inv * sG[i + 1] + sBe[i + 1];
        o4.z = (xs[i + 2] - m) * inv * sG[i + 2] + sBe[i + 2];
        o4.w = (xs[i + 3] - m) * inv * sG[i + 3] + sBe[i + 3];
        *(float4*)&op[i] = o4;
    }
}

// ---------------------------------------------------------------------------
// Fused attention (f32x2): q-proj, dots, softmax, o, Wo, +bo, residual, LN1.
// 128 threads / 128-row tile. K/V staged in two 128-k halves -> 2 CTAs/SM.
__global__ __launch_bounds__(128, 2) void attn_kernel(const float* __restrict__ Wq,
                                                      const float* __restrict__ Wo,
                                                      const float* __restrict__ bo,
                                                      const float* __restrict__ g1,
                                                      const float* __restrict__ be1) {
    extern __shared__ float sm[];
    float* sK = sm;                   // 8192 (current k-half)
    float* sV = sK + 8192;            // 8192
    float* sWq = sV + 8192;           // 4096
    float* sWo = sWq + 4096;          // 4096
    float* sBo = sWo + 4096;          // 64
    float* sG = sBo + DD;             // 64
    float* sBe = sG + DD;             // 64
    int b = blockIdx.y, t = threadIdx.x;

    for (int i = t * 4; i < DD * DD; i += 512) {
        *(float4*)&sWq[i] = *(const float4*)&Wq[i];
        *(float4*)&sWo[i] = *(const float4*)&Wo[i];
    }
    if (t < 16) {
        *(float4*)&sBo[t * 4] = *(const float4*)&bo[t * 4];
        *(float4*)&sG[t * 4] = *(const float4*)&g1[t * 4];
        *(float4*)&sBe[t * 4] = *(const float4*)&be1[t * 4];
    }
    const float* kb = g_k + (size_t)b * KK * DD;
    const float* vb = g_v + (size_t)b * KK * DD;
    for (int i = t * 4; i < 8192; i += 512) {
        *(float4*)&sK[i] = *(const float4*)&kb[i];
        *(float4*)&sV[i] = *(const float4*)&vb[i];
    }
    __syncthreads();

    int n = blockIdx.x * 128 + t;
    bool act = n < NN;
    float* xp = g_x + ((size_t)b * NN + n) * DD;

    u64 q2[32], oh2[32];
    float l[HH];

    if (act) {
        // q = x @ Wq (x row held temporarily)
        u64 xr2[32];
        const ulonglong2* xg = (const ulonglong2*)xp;
#pragma unroll
        for (int q = 0; q < 16; q++) {
            ulonglong2 v = xg[q];
            xr2[2 * q] = v.x; xr2[2 * q + 1] = v.y;
        }
#pragma unroll
        for (int jj = 0; jj < 32; jj++) q2[jj] = 0ull;
#pragma unroll
        for (int dd = 0; dd < 32; dd++) {
            float2 xv = up2(xr2[dd]);
            {
                u64 xb = bc2(xv.x);
                const ulonglong2* wr = (const ulonglong2*)&sWq[(2 * dd) * DD];
#pragma unroll
                for (int q = 0; q < 16; q++) {
                    ulonglong2 w = wr[q];
                    q2[2 * q] = f2fma(xb, w.x, q2[2 * q]);
                    q2[2 * q + 1] = f2fma(xb, w.y, q2[2 * q + 1]);
                }
            }
            {
                u64 xb = bc2(xv.y);
                const ulonglong2* wr = (const ulonglong2*)&sWq[(2 * dd + 1) * DD];
#pragma unroll
                for (int q = 0; q < 16; q++) {
                    ulonglong2 w = wr[q];
                    q2[2 * q] = f2fma(xb, w.x, q2[2 * q]);
                    q2[2 * q + 1] = f2fma(xb, w.y, q2[2 * q + 1]);
                }
            }
        }
#pragma unroll
        for (int jj = 0; jj < 32; jj++) oh2[jj] = 0ull;
#pragma unroll
        for (int h = 0; h < HH; h++) l[h] = 0.f;
    }

    // streaming softmax over two K/V halves
#pragma unroll 1
    for (int pass = 0; pass < 2; pass++) {
        if (pass == 1) {
            __syncthreads();
            for (int i = t * 4; i < 8192; i += 512) {
                *(float4*)&sK[i] = *(const float4*)&kb[8192 + i];
                *(float4*)&sV[i] = *(const float4*)&vb[8192 + i];
            }
            __syncthreads();
        }
        if (act) {
#pragma unroll
            for (int h = 0; h < HH; h++) {
#pragma unroll 2
                for (int k = 0; k < 128; k++) {
                    const ulonglong2* kr = (const ulonglong2*)&sK[k * DD + h * DHD];
                    ulonglong2 kA = kr[0], kB = kr[1], kC = kr[2], kD = kr[3];
                    u64 c0 = f2mul(q2[h * 8 + 0], kA.x);
                    u64 c1 = f2mul(q2[h * 8 + 1], kA.y);
                    c0 = f2fma(q2[h * 8 + 2], kB.x, c0);
                    c1 = f2fma(q2[h * 8 + 3], kB.y, c1);
                    c0 = f2fma(q2[h * 8 + 4], kC.x, c0);
                    c1 = f2fma(q2[h * 8 + 5], kC.y, c1);
                    c0 = f2fma(q2[h * 8 + 6], kD.x, c0);
                    c1 = f2fma(q2[h * 8 + 7], kD.y, c1);
                    float2 sv = up2(f2add(c0, c1));
                    float p = __expf((sv.x + sv.y) * 0.25f);
                    l[h] += p;
                    u64 pb = bc2(p);
                    const ulonglong2* vr = (const ulonglong2*)&sV[k * DD + h * DHD];
                    ulonglong2 vA = vr[0], vB = vr[1], vC = vr[2], vD = vr[3];
                    oh2[h * 8 + 0] = f2fma(pb, vA.x, oh2[h * 8 + 0]);
                    oh2[h * 8 + 1] = f2fma(pb, vA.y, oh2[h * 8 + 1]);
                    oh2[h * 8 + 2] = f2fma(pb, vB.x, oh2[h * 8 + 2]);
                    oh2[h * 8 + 3] = f2fma(pb, vB.y, oh2[h * 8 + 3]);
                    oh2[h * 8 + 4] = f2fma(pb, vC.x, oh2[h * 8 + 4]);
                    oh2[h * 8 + 5] = f2fma(pb, vC.y, oh2[h * 8 + 5]);
                    oh2[h * 8 + 6] = f2fma(pb, vD.x, oh2[h * 8 + 6]);
                    oh2[h * 8 + 7] = f2fma(pb, vD.y, oh2[h * 8 + 7]);
                }
            }
        }
    }

    if (act) {
        // reload residual row, add bo, fold Wo, LN
        u64 xr2[32];
        const ulonglong2* xg = (const ulonglong2*)xp;
#pragma unroll
        for (int q = 0; q < 16; q++) {
            ulonglong2 v = xg[q];
            xr2[2 * q] = v.x; xr2[2 * q + 1] = v.y;
        }
        const u64* bo2 = (const u64*)sBo;
#pragma unroll
        for (int jj = 0; jj < 32; jj++) xr2[jj] = f2add(xr2[jj], bo2[jj]);
#pragma unroll
        for (int h = 0; h < HH; h++) {
            float invl = 1.f / l[h];
#pragma unroll
            for (int jj = 0; jj < 8; jj++) {
                float2 ov = up2(oh2[h * 8 + jj]);
                {
                    u64 ob = bc2(ov.x * invl);
                    const ulonglong2* wr =
                        (const ulonglong2*)&sWo[(h * DHD + 2 * jj) * DD];
#pragma unroll
                    for (int q = 0; q < 16; q++) {
                        ulonglong2 w = wr[q];
                        xr2[2 * q] = f2fma(ob, w.x, xr2[2 * q]);
                        xr2[2 * q + 1] = f2fma(ob, w.y, xr2[2 * q + 1]);
                    }
                }
                {
                    u64 ob = bc2(ov.y * invl);
                    const ulonglong2* wr =
                        (const ulonglong2*)&sWo[(h * DHD + 2 * jj + 1) * DD];
#pragma unroll
                    for (int q = 0; q < 16; q++) {
                        ulonglong2 w = wr[q];
                        xr2[2 * q] = f2fma(ob, w.x, xr2[2 * q]);
                        xr2[2 * q + 1] = f2fma(ob, w.y, xr2[2 * q + 1]);
                    }
                }
            }
        }
        ln_store(xr2, sG, sBe, xp);
    }
}

// ---------------------------------------------------------------------------
// Fused FFN (f32x2): h = gelu(x@W1+b1); f = h@W2+b2; LN2(f+x).
// 128 threads / 128-row tile. W1/W2 staged in two 128-f halves -> 2+ CTAs/SM.
__global__ __launch_bounds__(128, 2) void ffn_kernel(const float* __restrict__ W1,
                                                     const float* __restrict__ b1,
                                                     const float* __restrict__ W2,
                                                     const float* __restrict__ b2,
                                                     const float* __restrict__ g2,
                                                     const float* __restrict__ be2,
                                                     float* __restrict__ xout) {
    extern __shared__ float sm[];
    float* sW1 = sm;                  // 8192 : [64][128] f-half slice
    float* sW2 = sW1 + 8192;          // 8192 : [128][64]
    float* sB1 = sW2 + 8192;          // 128
    float* sB2 = sB1 + 128;           // 64
    float* sG = sB2 + DD;             // 64
    float* sBe = sG + DD;             // 64
    int b = blockIdx.y, t = threadIdx.x;

    if (t < 16) {
        *(float4*)&sB2[t * 4] = *(const float4*)&b2[t * 4];
        *(float4*)&sG[t * 4] = *(const float4*)&g2[t * 4];
        *(float4*)&sBe[t * 4] = *(const float4*)&be2[t * 4];
    }
    int n = blockIdx.x * 128 + t;
    bool act = n < NN;
    const float* xp = g_x + ((size_t)b * NN + n) * DD;

    u64 xr2[32], facc2[32];
    if (act) {
        const ulonglong2* xg = (const ulonglong2*)xp;
#pragma unroll
        for (int q = 0; q < 16; q++) {
            ulonglong2 v = xg[q];
            xr2[2 * q] = v.x; xr2[2 * q + 1] = v.y;
        }
#pragma unroll
        for (int jj = 0; jj < 32; jj++) facc2[jj] = 0ull;
    }

#pragma unroll 1
    for (int half = 0; half < 2; half++) {
        int f0 = half * 128;
        if (half) __syncthreads();
        for (int i = t * 4; i < 8192; i += 512) {
            int d = i >> 7, c = i & 127;
            *(float4*)&sW1[i] = *(const float4*)&W1[d * FF + f0 + c];
        }
        for (int i = t * 4; i < 8192; i += 512)
            *(float4*)&sW2[i] = *(const float4*)&W2[f0 * DD + i];
        if (t < 32) *(float4*)&sB1[t * 4] = *(const float4*)&b1[f0 + t * 4];
        __syncthreads();

        if (act) {
            for (int fb = 0; fb < 128; fb += 8) {
                const u64* b1p = (const u64*)&sB1[fb];
                u64 h0 = b1p[0], h1 = b1p[1], h2 = b1p[2], h3 = b1p[3];
#pragma unroll
                for (int dd = 0; dd < 32; dd++) {
                    float2 xv = up2(xr2[dd]);
                    {
                        u64 xb = bc2(xv.x);
                        const ulonglong2* wr =
                            (const ulonglong2*)&sW1[(2 * dd) * 128 + fb];
                        ulonglong2 wA = wr[0], wB = wr[1];
                        h0 = f2fma(xb, wA.x, h0); h1 = f2fma(xb, wA.y, h1);
                        h2 = f2fma(xb, wB.x, h2); h3 = f2fma(xb, wB.y, h3);
                    }
                    {
                        u64 xb = bc2(xv.y);
                        const ulonglong2* wr =
                            (const ulonglong2*)&sW1[(2 * dd + 1) * 128 + fb];
                        ulonglong2 wA = wr[0], wB = wr[1];
                        h0 = f2fma(xb, wA.x, h0); h1 = f2fma(xb, wA.y, h1);
                        h2 = f2fma(xb, wB.x, h2); h3 = f2fma(xb, wB.y, h3);
                    }
                }
                float hs[8];
                { float2 v = up2(h0); hs[0] = v.x; hs[1] = v.y; }
                { float2 v = up2(h1); hs[2] = v.x; hs[3] = v.y; }
                { float2 v = up2(h2); hs[4] = v.x; hs[5] = v.y; }
                { float2 v = up2(h3); hs[6] = v.x; hs[7] = v.y; }
#pragma unroll
                for (int c = 0; c < 8; c++)
                    hs[c] = 0.5f * hs[c] *
                            (1.f + erff(hs[c] * 0.70710678118654752440f));
#pragma unroll
                for (int c = 0; c < 8; c++) {
                    u64 hb = bc2(hs[c]);
                    const ulonglong2* wr = (const ulonglong2*)&sW2[(fb + c) * DD];
#pragma unroll
                    for (int q = 0; q < 16; q++) {
                        ulonglong2 w = wr[q];
                        facc2[2 * q] = f2fma(hb, w.x, facc2[2 * q]);
                        facc2[2 * q + 1] = f2fma(hb, w.y, facc2[2 * q + 1]);
                    }
                }
            }
        }
    }

    if (act) {
        const u64* b2p = (const u64*)sB2;
#pragma unroll
        for (int jj = 0; jj < 32; jj++)
            xr2[jj] = f2add(xr2[jj], f2add(facc2[jj], b2p[jj]));
        ln_store(xr2, sG, sBe, xout + ((size_t)b * NN + n) * DD);
    }
}

// ---------------------------------------------------------------------------
extern "C" void kernel_launch(void* const* d_in, const int* in_sizes, int n_in,
                              void* d_out, int out_size) {
    const float* expr = (const float*)d_in[0];
    const float* emb = (const float*)d_in[1];
    const float* Wq = (const float*)d_in[2];
    const float* Wk = (const float*)d_in[3];
    const float* Wv = (const float*)d_in[4];
    const float* projK = (const float*)d_in[5];
    const float* projV = (const float*)d_in[6];
    const float* Wo = (const float*)d_in[7];
    const float* bo = (const float*)d_in[8];
    const float* g1 = (const float*)d_in[9];
    const float* be1 = (const float*)d_in[10];
    const float* W1 = (const float*)d_in[11];
    const float* bf1 = (const float*)d_in[12];
    const float* W2 = (const float*)d_in[13];
    const float* bf2 = (const float*)d_in[14];
    const float* g2 = (const float*)d_in[15];
    const float* be2 = (const float*)d_in[16];
    float* out = (float*)d_out;

    void* xaddr = nullptr;
    cudaGetSymbolAddress(&xaddr, g_x);
    float* gx = (float*)xaddr;

    cudaFuncSetAttribute(attn_kernel, cudaFuncAttributeMaxDynamicSharedMemorySize,
                         ATTN_SMEM_BYTES);
    cudaFuncSetAttribute(ffn_kernel, cudaFuncAttributeMaxDynamicSharedMemorySize,
                         FFN_SMEM_BYTES);

    embed_kernel<<<(BB * NN + 255) / 256, 256>>>(expr, emb);

    for (int l = 0; l < LLAYERS; l++) {
        proj_kernel<<<dim3(NSPLIT, BB, 2), 256>>>(projK + (size_t)l * NN * KK,
                                                  projV + (size_t)l * NN * KK);
        reduce_kernel<<<(2 * BB * KK * DD) / 256, 256>>>();
        kvproj_kernel<<<dim3(KK / 4, BB, 2), 256>>>(Wk + l * DD * DD,
                                                    Wv + l * DD * DD);
        attn_kernel<<<dim3(ROWT, BB), 128, ATTN_SMEM_BYTES>>>(
            Wq + l * DD * DD, Wo + l * DD * DD, bo + l * DD, g1 + l * DD,
            be1 + l * DD);
        ffn_kernel<<<dim3(ROWT, BB), 128, FFN_SMEM_BYTES>>>(
            W1 + l * DD * FF, bf1 + l * FF, W2 + l * FF * DD, bf2 + l * DD,
            g2 + l * DD, be2 + l * DD, (l == LLAYERS - 1) ? out : gx);
    }
}

// round 7
// speedup vs baseline: 1.6769x; 1.4078x over previous
#include <cuda_runtime.h>
#include <cuda_bf16.h>
#include <math.h>

// Problem constants
#define BB 4
#define NN 20000
#define DD 64
#define KK 256
#define HH 4
#define DHD 16
#define FF 256
#define LLAYERS 2
#define NSPLIT 37                    // 37*4*2 = 296 CTAs = exactly 2/SM
#define NTILES 148                   // attn/ffn row tiles per batch

// attn smem: K half 8192 + V half 8192 + Wq 4096 + Wo 4096 + bo/g/be 192
#define ATTN_SMEM_FLOATS (8192 + 8192 + 4096 + 4096 + 64 + 64 + 64)
#define ATTN_SMEM_BYTES (ATTN_SMEM_FLOATS * 4)                        // 99072
// ffn smem: W1T half 8192 + W2 half 8192 + b1 half 128 + b2/g/be 192
#define FFN_SMEM_FLOATS (8192 + 8192 + 128 + 64 + 64 + 64)
#define FFN_SMEM_BYTES (FFN_SMEM_FLOATS * 4)                          // 66816

typedef unsigned long long u64;

__device__ __forceinline__ u64 pk2(float a, float b) {
    u64 r; asm("mov.b64 %0,{%1,%2};" : "=l"(r) : "f"(a), "f"(b)); return r;
}
__device__ __forceinline__ u64 bc2(float a) { return pk2(a, a); }
__device__ __forceinline__ float2 up2(u64 v) {
    float2 r; asm("mov.b64 {%0,%1},%2;" : "=f"(r.x), "=f"(r.y) : "l"(v)); return r;
}
__device__ __forceinline__ u64 f2fma(u64 a, u64 b, u64 c) {
    u64 d; asm("fma.rn.f32x2 %0,%1,%2,%3;" : "=l"(d) : "l"(a), "l"(b), "l"(c)); return d;
}
__device__ __forceinline__ u64 f2add(u64 a, u64 b) {
    u64 d; asm("add.rn.f32x2 %0,%1,%2;" : "=l"(d) : "l"(a), "l"(b)); return d;
}
__device__ __forceinline__ u64 f2mul(u64 a, u64 b) {
    u64 d; asm("mul.rn.f32x2 %0,%1,%2;" : "=l"(d) : "l"(a), "l"(b)); return d;
}

// Scratch (module-scope device arrays; no runtime allocation)
__device__ float g_x[BB * NN * DD];                 // activations  [B,N,D]
__device__ float g_part[NSPLIT * 2 * BB * KK * DD]; // split-N partials
__device__ float g_kvlow[2 * BB * KK * DD];         // reduced k_low / v_low
__device__ float g_k[BB * KK * DD];                 // k = k_low @ Wk
__device__ float g_v[BB * KK * DD];                 // v = v_low @ Wv
__device__ float g_w1t[LLAYERS * FF * DD];          // W1 transposed [l][f][d]

// ---------------------------------------------------------------------------
// x[b,n,d] = emb[n,d] * expr[b,n]
__global__ void embed_kernel(const float* __restrict__ expr,
                             const float* __restrict__ emb) {
    int idx = blockIdx.x * blockDim.x + threadIdx.x;
    if (idx >= BB * NN) return;
    int b = idx / NN, n = idx % NN;
    float e = expr[b * NN + n];
    const float4* er = (const float4*)&emb[(size_t)n * DD];
    float4* xo = (float4*)&g_x[(size_t)idx * DD];
#pragma unroll
    for (int i = 0; i < DD / 4; i++) {
        float4 v = er[i];
        v.x *= e; v.y *= e; v.z *= e; v.w *= e;
        xo[i] = v;
    }
}

// ---------------------------------------------------------------------------
// W1T[l][f][d] = W1[l][d][f]  (both layers, once)
__global__ void w1t_kernel(const float* __restrict__ W1) {
    int idx = blockIdx.x * 256 + threadIdx.x;
    if (idx >= LLAYERS * FF * DD) return;
    int d = idx & 63;
    int f = (idx >> 6) & 255;
    int l = idx >> 14;
    g_w1t[idx] = W1[l * DD * FF + d * FF + f];
}

// ---------------------------------------------------------------------------
// Split-N low-rank projection, conflict-free mapping:
//   part[s,mat,b,k,d] = sum_{n in chunk s} P[n,k] * x[b,n,d]
// Thread t: kq = t&63 owns 4 consecutive k (lane-contiguous sP float4 loads);
//           td = t>>6 owns 16 consecutive d (warp-uniform broadcast sX loads).
__global__ __launch_bounds__(256) void proj_kernel(const float* __restrict__ PK,
                                                   const float* __restrict__ PV) {
    int s = blockIdx.x, b = blockIdx.y, mat = blockIdx.z;
    const float* P = (mat == 0) ? PK : PV;
    __shared__ float sP[16][KK];   // 16 KB
    __shared__ float sX[16][DD];   // 4 KB
    int t = threadIdx.x;
    int kq = t & 63;               // k base = kq*4
    int td = t >> 6;               // d base = td*16
    u64 acc[4][8];
#pragma unroll
    for (int i = 0; i < 4; i++)
#pragma unroll
        for (int j = 0; j < 8; j++) acc[i][j] = 0ull;

    int n0 = (s * NN) / NSPLIT;
    int n1 = ((s + 1) * NN) / NSPLIT;
    const float4 z4 = make_float4(0.f, 0.f, 0.f, 0.f);

    for (int n = n0; n < n1; n += 16) {
        // stage 16 P rows (4096 floats): 4 float4 per thread, coalesced
#pragma unroll
        for (int r4 = 0; r4 < 4; r4++) {
            int i = (t + r4 * 256) * 4;
            int row = i >> 8, col = i & 255;
            int nr = n + row;
            *(float4*)&sP[row][col] =
                (nr < n1) ? *(const float4*)&P[(size_t)nr * KK + col] : z4;
        }
        {   // stage 16 x rows (1024 floats): 1 float4 per thread
            int i = t * 4;
            int row = i >> 6, col = i & 63;
            int nr = n + row;
            *(float4*)&sX[row][col] =
                (nr < n1) ? *(const float4*)&g_x[((size_t)b * NN + nr) * DD + col]
                          : z4;
        }
        __syncthreads();
#pragma unroll
        for (int j = 0; j < 16; j++) {
            float4 pv = *(float4*)&sP[j][kq * 4];       // conflict-free
            u64 p0 = bc2(pv.x), p1 = bc2(pv.y), p2 = bc2(pv.z), p3 = bc2(pv.w);
            const ulonglong2* xp2 = (const ulonglong2*)&sX[j][td * 16];  // bcast
            ulonglong2 xa = xp2[0], xb = xp2[1], xc = xp2[2], xd = xp2[3];
            acc[0][0] = f2fma(p0, xa.x, acc[0][0]);
            acc[0][1] = f2fma(p0, xa.y, acc[0][1]);
            acc[0][2] = f2fma(p0, xb.x, acc[0][2]);
            acc[0][3] = f2fma(p0, xb.y, acc[0][3]);
            acc[0][4] = f2fma(p0, xc.x, acc[0][4]);
            acc[0][5] = f2fma(p0, xc.y, acc[0][5]);
            acc[0][6] = f2fma(p0, xd.x, acc[0][6]);
            acc[0][7] = f2fma(p0, xd.y, acc[0][7]);
            acc[1][0] = f2fma(p1, xa.x, acc[1][0]);
            acc[1][1] = f2fma(p1, xa.y, acc[1][1]);
            acc[1][2] = f2fma(p1, xb.x, acc[1][2]);
            acc[1][3] = f2fma(p1, xb.y, acc[1][3]);
            acc[1][4] = f2fma(p1, xc.x, acc[1][4]);
            acc[1][5] = f2fma(p1, xc.y, acc[1][5]);
            acc[1][6] = f2fma(p1, xd.x, acc[1][6]);
            acc[1][7] = f2fma(p1, xd.y, acc[1][7]);
            acc[2][0] = f2fma(p2, xa.x, acc[2][0]);
            acc[2][1] = f2fma(p2, xa.y, acc[2][1]);
            acc[2][2] = f2fma(p2, xb.x, acc[2][2]);
            acc[2][3] = f2fma(p2, xb.y, acc[2][3]);
            acc[2][4] = f2fma(p2, xc.x, acc[2][4]);
            acc[2][5] = f2fma(p2, xc.y, acc[2][5]);
            acc[2][6] = f2fma(p2, xd.x, acc[2][6]);
            acc[2][7] = f2fma(p2, xd.y, acc[2][7]);
            acc[3][0] = f2fma(p3, xa.x, acc[3][0]);
            acc[3][1] = f2fma(p3, xa.y, acc[3][1]);
            acc[3][2] = f2fma(p3, xb.x, acc[3][2]);
            acc[3][3] = f2fma(p3, xb.y, acc[3][3]);
            acc[3][4] = f2fma(p3, xc.x, acc[3][4]);
            acc[3][5] = f2fma(p3, xc.y, acc[3][5]);
            acc[3][6] = f2fma(p3, xd.x, acc[3][6]);
            acc[3][7] = f2fma(p3, xd.y, acc[3][7]);
        }
        __syncthreads();
    }
    float* o = g_part + (((size_t)s * 2 + mat) * BB + b) * (KK * DD);
#pragma unroll
    for (int i = 0; i < 4; i++) {
        int k = kq * 4 + i;
        ulonglong2* op = (ulonglong2*)&o[k * DD + td * 16];
        op[0] = make_ulonglong2(acc[i][0], acc[i][1]);
        op[1] = make_ulonglong2(acc[i][2], acc[i][3]);
        op[2] = make_ulonglong2(acc[i][4], acc[i][5]);
        op[3] = make_ulonglong2(acc[i][6], acc[i][7]);
    }
}

// ---------------------------------------------------------------------------
__global__ void reduce_kernel() {
    int idx = blockIdx.x * blockDim.x + threadIdx.x;
    if (idx >= 2 * BB * KK * DD) return;
    float sum = 0.f;
    for (int s = 0; s < NSPLIT; s++)
        sum += g_part[(size_t)s * (2 * BB * KK * DD) + idx];
    g_kvlow[idx] = sum;
}

// ---------------------------------------------------------------------------
__global__ void kvproj_kernel(const float* __restrict__ Wk,
                              const float* __restrict__ Wv) {
    int mat = blockIdx.z, b = blockIdx.y;
    const float* W = (mat == 0) ? Wk : Wv;
    __shared__ float sW[DD * DD];
    __shared__ float sL[4][DD];
    int t = threadIdx.x;
    for (int i = t * 4; i < DD * DD; i += 1024)
        *(float4*)&sW[i] = *(const float4*)&W[i];
    if (t < 64) {
        int r = t >> 4, c = (t & 15) * 4;
        int k = blockIdx.x * 4 + r;
        *(float4*)&sL[r][c] =
            *(const float4*)&g_kvlow[((size_t)mat * BB + b) * KK * DD + k * DD + c];
    }
    __syncthreads();
    int e = t & 63, kr = t >> 6;
    int k = blockIdx.x * 4 + kr;
    float sacc = 0.f;
#pragma unroll
    for (int d = 0; d < DD; d++) sacc += sL[kr][d] * sW[d * DD + e];
    float* out = (mat == 0) ? g_k : g_v;
    out[(size_t)b * KK * DD + k * DD + e] = sacc;
}

// ---------------------------------------------------------------------------
__device__ __forceinline__ void ln_store(u64* xr2, const float* sG,
                                         const float* sBe, float* op) {
    float xs[DD];
#pragma unroll
    for (int jj = 0; jj < 32; jj++) {
        float2 v = up2(xr2[jj]);
        xs[2 * jj] = v.x; xs[2 * jj + 1] = v.y;
    }
    float m = 0.f;
#pragma unroll
    for (int d = 0; d < DD; d++) m += xs[d];
    m *= (1.f / DD);
    float var = 0.f;
#pragma unroll
    for (int d = 0; d < DD; d++) { float df = xs[d] - m; var += df * df; }
    var *= (1.f / DD);
    float inv = rsqrtf(var + 1e-5f);
#pragma unroll
    for (int i = 0; i < DD; i += 4) {
        float4 o4;
        o4.x = (xs[i] - m) * inv * sG[i] + sBe[i];
        o4.y = (xs[i + 1] - m) * inv * sG[i + 1] + sBe[i + 1];
        o4.z = (xs[i + 2] - m) * inv * sG[i + 2] + sBe[i + 2];
        o4.w = (xs[i + 3] - m) * inv * sG[i + 3] + sBe[i + 3];
        *(float4*)&op[i] = o4;
    }
}

// ---------------------------------------------------------------------------
// Fused attention. grid (148, B): balanced row ranges, 2 clean waves at occ 2.
__global__ __launch_bounds__(128, 2) void attn_kernel(const float* __restrict__ Wq,
                                                      const float* __restrict__ Wo,
                                                      const float* __restrict__ bo,
                                                      const float* __restrict__ g1,
                                                      const float* __restrict__ be1) {
    extern __shared__ float sm[];
    float* sK = sm;                   // 8192 (current k-half)
    float* sV = sK + 8192;            // 8192
    float* sWq = sV + 8192;           // 4096
    float* sWo = sWq + 4096;          // 4096
    float* sBo = sWo + 4096;          // 64
    float* sG = sBo + DD;             // 64
    float* sBe = sG + DD;             // 64
    int b = blockIdx.y, t = threadIdx.x;

    for (int i = t * 4; i < DD * DD; i += 512) {
        *(float4*)&sWq[i] = *(const float4*)&Wq[i];
        *(float4*)&sWo[i] = *(const float4*)&Wo[i];
    }
    if (t < 16) {
        *(float4*)&sBo[t * 4] = *(const float4*)&bo[t * 4];
        *(float4*)&sG[t * 4] = *(const float4*)&g1[t * 4];
        *(float4*)&sBe[t * 4] = *(const float4*)&be1[t * 4];
    }
    const float* kb = g_k + (size_t)b * KK * DD;
    const float* vb = g_v + (size_t)b * KK * DD;

    int r0 = (blockIdx.x * NN) / NTILES;
    int r1 = ((blockIdx.x + 1) * NN) / NTILES;

    for (int nb = r0; nb < r1; nb += 128) {
        int n = nb + t;
        bool act = n < r1;
        float* xp = g_x + ((size_t)b * NN + n) * DD;

        u64 q2[32], oh2[32];
        float l[HH];

        if (act) {
            u64 xr2[32];
            const ulonglong2* xg = (const ulonglong2*)xp;
#pragma unroll
            for (int q = 0; q < 16; q++) {
                ulonglong2 v = xg[q];
                xr2[2 * q] = v.x; xr2[2 * q + 1] = v.y;
            }
#pragma unroll
            for (int jj = 0; jj < 32; jj++) q2[jj] = 0ull;
#pragma unroll
            for (int dd = 0; dd < 32; dd++) {
                float2 xv = up2(xr2[dd]);
                {
                    u64 xb = bc2(xv.x);
                    const ulonglong2* wr = (const ulonglong2*)&sWq[(2 * dd) * DD];
#pragma unroll
                    for (int q = 0; q < 16; q++) {
                        ulonglong2 w = wr[q];
                        q2[2 * q] = f2fma(xb, w.x, q2[2 * q]);
                        q2[2 * q + 1] = f2fma(xb, w.y, q2[2 * q + 1]);
                    }
                }
                {
                    u64 xb = bc2(xv.y);
                    const ulonglong2* wr = (const ulonglong2*)&sWq[(2 * dd + 1) * DD];
#pragma unroll
                    for (int q = 0; q < 16; q++) {
                        ulonglong2 w = wr[q];
                        q2[2 * q] = f2fma(xb, w.x, q2[2 * q]);
                        q2[2 * q + 1] = f2fma(xb, w.y, q2[2 * q + 1]);
                    }
                }
            }
#pragma unroll
            for (int jj = 0; jj < 32; jj++) oh2[jj] = 0ull;
#pragma unroll
            for (int h = 0; h < HH; h++) l[h] = 0.f;
        }

#pragma unroll 1
        for (int pass = 0; pass < 2; pass++) {
            __syncthreads();
            for (int i = t * 4; i < 8192; i += 512) {
                *(float4*)&sK[i] = *(const float4*)&kb[pass * 8192 + i];
                *(float4*)&sV[i] = *(const float4*)&vb[pass * 8192 + i];
            }
            __syncthreads();
            if (act) {
#pragma unroll
                for (int h = 0; h < HH; h++) {
#pragma unroll 2
                    for (int k = 0; k < 128; k++) {
                        const ulonglong2* kr =
                            (const ulonglong2*)&sK[k * DD + h * DHD];
                        ulonglong2 kA = kr[0], kB = kr[1], kC = kr[2], kD = kr[3];
                        u64 c0 = f2mul(q2[h * 8 + 0], kA.x);
                        u64 c1 = f2mul(q2[h * 8 + 1], kA.y);
                        c0 = f2fma(q2[h * 8 + 2], kB.x, c0);
                        c1 = f2fma(q2[h * 8 + 3], kB.y, c1);
                        c0 = f2fma(q2[h * 8 + 4], kC.x, c0);
                        c1 = f2fma(q2[h * 8 + 5], kC.y, c1);
                        c0 = f2fma(q2[h * 8 + 6], kD.x, c0);
                        c1 = f2fma(q2[h * 8 + 7], kD.y, c1);
                        float2 sv = up2(f2add(c0, c1));
                        float p = __expf((sv.x + sv.y) * 0.25f);
                        l[h] += p;
                        u64 pb = bc2(p);
                        const ulonglong2* vr =
                            (const ulonglong2*)&sV[k * DD + h * DHD];
                        ulonglong2 vA = vr[0], vB = vr[1], vC = vr[2], vD = vr[3];
                        oh2[h * 8 + 0] = f2fma(pb, vA.x, oh2[h * 8 + 0]);
                        oh2[h * 8 + 1] = f2fma(pb, vA.y, oh2[h * 8 + 1]);
                        oh2[h * 8 + 2] = f2fma(pb, vB.x, oh2[h * 8 + 2]);
                        oh2[h * 8 + 3] = f2fma(pb, vB.y, oh2[h * 8 + 3]);
                        oh2[h * 8 + 4] = f2fma(pb, vC.x, oh2[h * 8 + 4]);
                        oh2[h * 8 + 5] = f2fma(pb, vC.y, oh2[h * 8 + 5]);
                        oh2[h * 8 + 6] = f2fma(pb, vD.x, oh2[h * 8 + 6]);
                        oh2[h * 8 + 7] = f2fma(pb, vD.y, oh2[h * 8 + 7]);
                    }
                }
            }
        }

        if (act) {
            u64 xr2[32];
            const ulonglong2* xg = (const ulonglong2*)xp;
#pragma unroll
            for (int q = 0; q < 16; q++) {
                ulonglong2 v = xg[q];
                xr2[2 * q] = v.x; xr2[2 * q + 1] = v.y;
            }
            const u64* bo2 = (const u64*)sBo;
#pragma unroll
            for (int jj = 0; jj < 32; jj++) xr2[jj] = f2add(xr2[jj], bo2[jj]);
#pragma unroll
            for (int h = 0; h < HH; h++) {
                float invl = 1.f / l[h];
#pragma unroll
                for (int jj = 0; jj < 8; jj++) {
                    float2 ov = up2(oh2[h * 8 + jj]);
                    {
                        u64 ob = bc2(ov.x * invl);
                        const ulonglong2* wr =
                            (const ulonglong2*)&sWo[(h * DHD + 2 * jj) * DD];
#pragma unroll
                        for (int q = 0; q < 16; q++) {
                            ulonglong2 w = wr[q];
                            xr2[2 * q] = f2fma(ob, w.x, xr2[2 * q]);
                            xr2[2 * q + 1] = f2fma(ob, w.y, xr2[2 * q + 1]);
                        }
                    }
                    {
                        u64 ob = bc2(ov.y * invl);
                        const ulonglong2* wr =
                            (const ulonglong2*)&sWo[(h * DHD + 2 * jj + 1) * DD];
#pragma unroll
                        for (int q = 0; q < 16; q++) {
                            ulonglong2 w = wr[q];
                            xr2[2 * q] = f2fma(ob, w.x, xr2[2 * q]);
                            xr2[2 * q + 1] = f2fma(ob, w.y, xr2[2 * q + 1]);
                        }
                    }
                }
            }
            ln_store(xr2, sG, sBe, xp);
        }
    }
}

// ---------------------------------------------------------------------------
// Fused FFN with transposed W1 (pair-packed dot, no broadcasts in W1 pass).
__global__ __launch_bounds__(128, 2) void ffn_kernel(const float* __restrict__ w1t,
                                                     const float* __restrict__ b1,
                                                     const float* __restrict__ W2,
                                                     const float* __restrict__ b2,
                                                     const float* __restrict__ g2,
                                                     const float* __restrict__ be2,
                                                     float* __restrict__ xout) {
    extern __shared__ float sm[];
    float* sW1 = sm;                  // 8192 : [128 f][64 d] f-half (transposed)
    float* sW2 = sW1 + 8192;          // 8192 : [128 f][64 d]
    float* sB1 = sW2 + 8192;          // 128
    float* sB2 = sB1 + 128;           // 64
    float* sG = sB2 + DD;             // 64
    float* sBe = sG + DD;             // 64
    int b = blockIdx.y, t = threadIdx.x;

    if (t < 16) {
        *(float4*)&sB2[t * 4] = *(const float4*)&b2[t * 4];
        *(float4*)&sG[t * 4] = *(const float4*)&g2[t * 4];
        *(float4*)&sBe[t * 4] = *(const float4*)&be2[t * 4];
    }

    int r0 = (blockIdx.x * NN) / NTILES;
    int r1 = ((blockIdx.x + 1) * NN) / NTILES;

    for (int nb = r0; nb < r1; nb += 128) {
        int n = nb + t;
        bool act = n < r1;
        const float* xp = g_x + ((size_t)b * NN + n) * DD;

        u64 xr2[32], facc2[32];
        if (act) {
            const ulonglong2* xg = (const ulonglong2*)xp;
#pragma unroll
            for (int q = 0; q < 16; q++) {
                ulonglong2 v = xg[q];
                xr2[2 * q] = v.x; xr2[2 * q + 1] = v.y;
            }
#pragma unroll
            for (int jj = 0; jj < 32; jj++) facc2[jj] = 0ull;
        }

#pragma unroll 1
        for (int half = 0; half < 2; half++) {
            int f0 = half * 128;
            __syncthreads();
            for (int i = t * 4; i < 8192; i += 512) {
                *(float4*)&sW1[i] = *(const float4*)&w1t[f0 * DD + i];
                *(float4*)&sW2[i] = *(const float4*)&W2[f0 * DD + i];
            }
            if (t < 32) *(float4*)&sB1[t * 4] = *(const float4*)&b1[f0 + t * 4];
            __syncthreads();

            if (act) {
                for (int fb = 0; fb < 128; fb += 8) {
                    u64 hacc[8];
#pragma unroll
                    for (int ff = 0; ff < 8; ff++) hacc[ff] = 0ull;
#pragma unroll
                    for (int q = 0; q < 32; q += 2) {
                        u64 x0 = xr2[q], x1 = xr2[q + 1];
#pragma unroll
                        for (int ff = 0; ff < 8; ff++) {
                            ulonglong2 w =
                                *(const ulonglong2*)&sW1[(fb + ff) * DD + q * 2];
                            hacc[ff] = f2fma(x0, w.x, hacc[ff]);
                            hacc[ff] = f2fma(x1, w.y, hacc[ff]);
                        }
                    }
                    float hs[8];
#pragma unroll
                    for (int ff = 0; ff < 8; ff++) {
                        float2 hv = up2(hacc[ff]);
                        float hval = hv.x + hv.y + sB1[fb + ff];
                        hs[ff] = 0.5f * hval *
                                 (1.f + erff(hval * 0.70710678118654752440f));
                    }
#pragma unroll
                    for (int c = 0; c < 8; c++) {
                        u64 hb = bc2(hs[c]);
                        const ulonglong2* wr =
                            (const ulonglong2*)&sW2[(fb + c) * DD];
#pragma unroll
                        for (int q = 0; q < 16; q++) {
                            ulonglong2 w = wr[q];
                            facc2[2 * q] = f2fma(hb, w.x, facc2[2 * q]);
                            facc2[2 * q + 1] = f2fma(hb, w.y, facc2[2 * q + 1]);
                        }
                    }
                }
            }
        }

        if (act) {
            const u64* b2p = (const u64*)sB2;
#pragma unroll
            for (int jj = 0; jj < 32; jj++)
                xr2[jj] = f2add(xr2[jj], f2add(facc2[jj], b2p[jj]));
            ln_store(xr2, sG, sBe, xout + ((size_t)b * NN + n) * DD);
        }
    }
}

// ---------------------------------------------------------------------------
extern "C" void kernel_launch(void* const* d_in, const int* in_sizes, int n_in,
                              void* d_out, int out_size) {
    const float* expr = (const float*)d_in[0];
    const float* emb = (const float*)d_in[1];
    const float* Wq = (const float*)d_in[2];
    const float* Wk = (const float*)d_in[3];
    const float* Wv = (const float*)d_in[4];
    const float* projK = (const float*)d_in[5];
    const float* projV = (const float*)d_in[6];
    const float* Wo = (const float*)d_in[7];
    const float* bo = (const float*)d_in[8];
    const float* g1 = (const float*)d_in[9];
    const float* be1 = (const float*)d_in[10];
    const float* W1 = (const float*)d_in[11];
    const float* bf1 = (const float*)d_in[12];
    const float* W2 = (const float*)d_in[13];
    const float* bf2 = (const float*)d_in[14];
    const float* g2 = (const float*)d_in[15];
    const float* be2 = (const float*)d_in[16];
    float* out = (float*)d_out;

    void* xaddr = nullptr;
    cudaGetSymbolAddress(&xaddr, g_x);
    float* gx = (float*)xaddr;
    void* w1taddr = nullptr;
    cudaGetSymbolAddress(&w1taddr, g_w1t);
    const float* gw1t = (const float*)w1taddr;

    cudaFuncSetAttribute(attn_kernel, cudaFuncAttributeMaxDynamicSharedMemorySize,
                         ATTN_SMEM_BYTES);
    cudaFuncSetAttribute(ffn_kernel, cudaFuncAttributeMaxDynamicSharedMemorySize,
                         FFN_SMEM_BYTES);

    embed_kernel<<<(BB * NN + 255) / 256, 256>>>(expr, emb);
    w1t_kernel<<<(LLAYERS * FF * DD + 255) / 256, 256>>>(W1);

    for (int l = 0; l < LLAYERS; l++) {
        proj_kernel<<<dim3(NSPLIT, BB, 2), 256>>>(projK + (size_t)l * NN * KK,
                                                  projV + (size_t)l * NN * KK);
        reduce_kernel<<<(2 * BB * KK * DD) / 256, 256>>>();
        kvproj_kernel<<<dim3(KK / 4, BB, 2), 256>>>(Wk + l * DD * DD,
                                                    Wv + l * DD * DD);
        attn_kernel<<<dim3(NTILES, BB), 128, ATTN_SMEM_BYTES>>>(
            Wq + l * DD * DD, Wo + l * DD * DD, bo + l * DD, g1 + l * DD,
            be1 + l * DD);
        ffn_kernel<<<dim3(NTILES, BB), 128, FFN_SMEM_BYTES>>>(
            gw1t + (size_t)l * FF * DD, bf1 + l * FF, W2 + (size_t)l * FF * DD,
            bf2 + l * DD, g2 + l * DD, be2 + l * DD,
            (l == LLAYERS - 1) ? out : gx);
    }
}

// round 8
// speedup vs baseline: 1.7641x; 1.0520x over previous
#include <cuda_runtime.h>
#include <cuda_bf16.h>
#include <math.h>

// Problem constants
#define BB 4
#define NN 20000
#define DD 64
#define KK 256
#define HH 4
#define DHD 16
#define FF 256
#define LLAYERS 2
#define NSPLIT 37                    // 37*4*2 = 296 CTAs = exactly 2/SM
#define ATILES 157                   // 157*128 = 20096 >= 20000, exact tiles

// attn smem: K quarter 4096 + V quarter 4096 + Wq 4096 + Wo 4096 + 192
#define ATTN_SMEM_FLOATS (4096 + 4096 + 4096 + 4096 + 64 + 64 + 64)
#define ATTN_SMEM_BYTES (ATTN_SMEM_FLOATS * 4)                        // 66304
// ffn smem: W1T half 8192 + W2 half 8192 + b1 half 128 + b2/g/be 192
#define FFN_SMEM_FLOATS (8192 + 8192 + 128 + 64 + 64 + 64)
#define FFN_SMEM_BYTES (FFN_SMEM_FLOATS * 4)                          // 66816

typedef unsigned long long u64;

__device__ __forceinline__ u64 pk2(float a, float b) {
    u64 r; asm("mov.b64 %0,{%1,%2};" : "=l"(r) : "f"(a), "f"(b)); return r;
}
__device__ __forceinline__ u64 bc2(float a) { return pk2(a, a); }
__device__ __forceinline__ float2 up2(u64 v) {
    float2 r; asm("mov.b64 {%0,%1},%2;" : "=f"(r.x), "=f"(r.y) : "l"(v)); return r;
}
__device__ __forceinline__ u64 f2fma(u64 a, u64 b, u64 c) {
    u64 d; asm("fma.rn.f32x2 %0,%1,%2,%3;" : "=l"(d) : "l"(a), "l"(b), "l"(c)); return d;
}
__device__ __forceinline__ u64 f2add(u64 a, u64 b) {
    u64 d; asm("add.rn.f32x2 %0,%1,%2;" : "=l"(d) : "l"(a), "l"(b)); return d;
}
__device__ __forceinline__ u64 f2mul(u64 a, u64 b) {
    u64 d; asm("mul.rn.f32x2 %0,%1,%2;" : "=l"(d) : "l"(a), "l"(b)); return d;
}

// Scratch (module-scope device arrays; no runtime allocation)
__device__ float g_x[BB * NN * DD];                 // activations  [B,N,D]
__device__ float g_part[NSPLIT * 2 * BB * KK * DD]; // split-N partials
__device__ float g_kvlow[2 * BB * KK * DD];         // reduced k_low / v_low
__device__ float g_k[BB * KK * DD];                 // k = k_low @ Wk
__device__ float g_v[BB * KK * DD];                 // v = v_low @ Wv
__device__ float g_w1t[LLAYERS * FF * DD];          // W1 transposed [l][f][d]

// ---------------------------------------------------------------------------
// x[b,n,d] = emb[n,d] * expr[b,n]
__global__ void embed_kernel(const float* __restrict__ expr,
                             const float* __restrict__ emb) {
    int idx = blockIdx.x * blockDim.x + threadIdx.x;
    if (idx >= BB * NN) return;
    int b = idx / NN, n = idx % NN;
    float e = expr[b * NN + n];
    const float4* er = (const float4*)&emb[(size_t)n * DD];
    float4* xo = (float4*)&g_x[(size_t)idx * DD];
#pragma unroll
    for (int i = 0; i < DD / 4; i++) {
        float4 v = er[i];
        v.x *= e; v.y *= e; v.z *= e; v.w *= e;
        xo[i] = v;
    }
}

// ---------------------------------------------------------------------------
// W1T[l][f][d] = W1[l][d][f]  (both layers, once)
__global__ void w1t_kernel(const float* __restrict__ W1) {
    int idx = blockIdx.x * 256 + threadIdx.x;
    if (idx >= LLAYERS * FF * DD) return;
    int d = idx & 63;
    int f = (idx >> 6) & 255;
    int l = idx >> 14;
    g_w1t[idx] = W1[l * DD * FF + d * FF + f];
}

// ---------------------------------------------------------------------------
// Split-N low-rank projection, conflict-free mapping:
//   part[s,mat,b,k,d] = sum_{n in chunk s} P[n,k] * x[b,n,d]
__global__ __launch_bounds__(256) void proj_kernel(const float* __restrict__ PK,
                                                   const float* __restrict__ PV) {
    int s = blockIdx.x, b = blockIdx.y, mat = blockIdx.z;
    const float* P = (mat == 0) ? PK : PV;
    __shared__ float sP[16][KK];   // 16 KB
    __shared__ float sX[16][DD];   // 4 KB
    int t = threadIdx.x;
    int kq = t & 63;               // k base = kq*4
    int td = t >> 6;               // d base = td*16
    u64 acc[4][8];
#pragma unroll
    for (int i = 0; i < 4; i++)
#pragma unroll
        for (int j = 0; j < 8; j++) acc[i][j] = 0ull;

    int n0 = (s * NN) / NSPLIT;
    int n1 = ((s + 1) * NN) / NSPLIT;
    const float4 z4 = make_float4(0.f, 0.f, 0.f, 0.f);

    for (int n = n0; n < n1; n += 16) {
#pragma unroll
        for (int r4 = 0; r4 < 4; r4++) {
            int i = (t + r4 * 256) * 4;
            int row = i >> 8, col = i & 255;
            int nr = n + row;
            *(float4*)&sP[row][col] =
                (nr < n1) ? *(const float4*)&P[(size_t)nr * KK + col] : z4;
        }
        {
            int i = t * 4;
            int row = i >> 6, col = i & 63;
            int nr = n + row;
            *(float4*)&sX[row][col] =
                (nr < n1) ? *(const float4*)&g_x[((size_t)b * NN + nr) * DD + col]
                          : z4;
        }
        __syncthreads();
#pragma unroll
        for (int j = 0; j < 16; j++) {
            float4 pv = *(float4*)&sP[j][kq * 4];       // conflict-free
            u64 p0 = bc2(pv.x), p1 = bc2(pv.y), p2 = bc2(pv.z), p3 = bc2(pv.w);
            const ulonglong2* xp2 = (const ulonglong2*)&sX[j][td * 16];  // bcast
            ulonglong2 xa = xp2[0], xb = xp2[1], xc = xp2[2], xd = xp2[3];
            acc[0][0] = f2fma(p0, xa.x, acc[0][0]);
            acc[0][1] = f2fma(p0, xa.y, acc[0][1]);
            acc[0][2] = f2fma(p0, xb.x, acc[0][2]);
            acc[0][3] = f2fma(p0, xb.y, acc[0][3]);
            acc[0][4] = f2fma(p0, xc.x, acc[0][4]);
            acc[0][5] = f2fma(p0, xc.y, acc[0][5]);
            acc[0][6] = f2fma(p0, xd.x, acc[0][6]);
            acc[0][7] = f2fma(p0, xd.y, acc[0][7]);
            acc[1][0] = f2fma(p1, xa.x, acc[1][0]);
            acc[1][1] = f2fma(p1, xa.y, acc[1][1]);
            acc[1][2] = f2fma(p1, xb.x, acc[1][2]);
            acc[1][3] = f2fma(p1, xb.y, acc[1][3]);
            acc[1][4] = f2fma(p1, xc.x, acc[1][4]);
            acc[1][5] = f2fma(p1, xc.y, acc[1][5]);
            acc[1][6] = f2fma(p1, xd.x, acc[1][6]);
            acc[1][7] = f2fma(p1, xd.y, acc[1][7]);
            acc[2][0] = f2fma(p2, xa.x, acc[2][0]);
            acc[2][1] = f2fma(p2, xa.y, acc[2][1]);
            acc[2][2] = f2fma(p2, xb.x, acc[2][2]);
            acc[2][3] = f2fma(p2, xb.y, acc[2][3]);
            acc[2][4] = f2fma(p2, xc.x, acc[2][4]);
            acc[2][5] = f2fma(p2, xc.y, acc[2][5]);
            acc[2][6] = f2fma(p2, xd.x, acc[2][6]);
            acc[2][7] = f2fma(p2, xd.y, acc[2][7]);
            acc[3][0] = f2fma(p3, xa.x, acc[3][0]);
            acc[3][1] = f2fma(p3, xa.y, acc[3][1]);
            acc[3][2] = f2fma(p3, xb.x, acc[3][2]);
            acc[3][3] = f2fma(p3, xb.y, acc[3][3]);
            acc[3][4] = f2fma(p3, xc.x, acc[3][4]);
            acc[3][5] = f2fma(p3, xc.y, acc[3][5]);
            acc[3][6] = f2fma(p3, xd.x, acc[3][6]);
            acc[3][7] = f2fma(p3, xd.y, acc[3][7]);
        }
        __syncthreads();
    }
    float* o = g_part + (((size_t)s * 2 + mat) * BB + b) * (KK * DD);
#pragma unroll
    for (int i = 0; i < 4; i++) {
        int k = kq * 4 + i;
        ulonglong2* op = (ulonglong2*)&o[k * DD + td * 16];
        op[0] = make_ulonglong2(acc[i][0], acc[i][1]);
        op[1] = make_ulonglong2(acc[i][2], acc[i][3]);
        op[2] = make_ulonglong2(acc[i][4], acc[i][5]);
        op[3] = make_ulonglong2(acc[i][6], acc[i][7]);
    }
}

// ---------------------------------------------------------------------------
__global__ void reduce_kernel() {
    int idx = blockIdx.x * blockDim.x + threadIdx.x;
    if (idx >= 2 * BB * KK * DD) return;
    float sum = 0.f;
    for (int s = 0; s < NSPLIT; s++)
        sum += g_part[(size_t)s * (2 * BB * KK * DD) + idx];
    g_kvlow[idx] = sum;
}

// ---------------------------------------------------------------------------
__global__ void kvproj_kernel(const float* __restrict__ Wk,
                              const float* __restrict__ Wv) {
    int mat = blockIdx.z, b = blockIdx.y;
    const float* W = (mat == 0) ? Wk : Wv;
    __shared__ float sW[DD * DD];
    __shared__ float sL[4][DD];
    int t = threadIdx.x;
    for (int i = t * 4; i < DD * DD; i += 1024)
        *(float4*)&sW[i] = *(const float4*)&W[i];
    if (t < 64) {
        int r = t >> 4, c = (t & 15) * 4;
        int k = blockIdx.x * 4 + r;
        *(float4*)&sL[r][c] =
            *(const float4*)&g_kvlow[((size_t)mat * BB + b) * KK * DD + k * DD + c];
    }
    __syncthreads();
    int e = t & 63, kr = t >> 6;
    int k = blockIdx.x * 4 + kr;
    float sacc = 0.f;
#pragma unroll
    for (int d = 0; d < DD; d++) sacc += sL[kr][d] * sW[d * DD + e];
    float* out = (mat == 0) ? g_k : g_v;
    out[(size_t)b * KK * DD + k * DD + e] = sacc;
}

// ---------------------------------------------------------------------------
__device__ __forceinline__ void ln_store(u64* xr2, const float* sG,
                                         const float* sBe, float* op) {
    float xs[DD];
#pragma unroll
    for (int jj = 0; jj < 32; jj++) {
        float2 v = up2(xr2[jj]);
        xs[2 * jj] = v.x; xs[2 * jj + 1] = v.y;
    }
    float m = 0.f;
#pragma unroll
    for (int d = 0; d < DD; d++) m += xs[d];
    m *= (1.f / DD);
    float var = 0.f;
#pragma unroll
    for (int d = 0; d < DD; d++) { float df = xs[d] - m; var += df * df; }
    var *= (1.f / DD);
    float inv = rsqrtf(var + 1e-5f);
#pragma unroll
    for (int i = 0; i < DD; i += 4) {
        float4 o4;
        o4.x = (xs[i] - m) * inv * sG[i] + sBe[i];
        o4.y = (xs[i + 1] - m) * inv * sG[i + 1] + sBe[i + 1];
        o4.z = (xs[i + 2] - m) * inv * sG[i + 2] + sBe[i + 2];
        o4.w = (xs[i + 3] - m) * inv * sG[i + 3] + sBe[i + 3];
        *(float4*)&op[i] = o4;
    }
}

// ---------------------------------------------------------------------------
// Fused attention. grid (157, B): exact 128-row tiles (warp-efficient), occ 3.
// K/V staged in four 64-k quarters to fit 65 KB smem.
__global__ __launch_bounds__(128, 3) void attn_kernel(const float* __restrict__ Wq,
                                                      const float* __restrict__ Wo,
                                                      const float* __restrict__ bo,
                                                      const float* __restrict__ g1,
                                                      const float* __restrict__ be1) {
    extern __shared__ float sm[];
    float* sK = sm;                   // 4096 (current 64-k quarter)
    float* sV = sK + 4096;            // 4096
    float* sWq = sV + 4096;           // 4096
    float* sWo = sWq + 4096;          // 4096
    float* sBo = sWo + 4096;          // 64
    float* sG = sBo + DD;             // 64
    float* sBe = sG + DD;             // 64
    int b = blockIdx.y, t = threadIdx.x;

    for (int i = t * 4; i < DD * DD; i += 512) {
        *(float4*)&sWq[i] = *(const float4*)&Wq[i];
        *(float4*)&sWo[i] = *(const float4*)&Wo[i];
    }
    if (t < 16) {
        *(float4*)&sBo[t * 4] = *(const float4*)&bo[t * 4];
        *(float4*)&sG[t * 4] = *(const float4*)&g1[t * 4];
        *(float4*)&sBe[t * 4] = *(const float4*)&be1[t * 4];
    }
    const float* kb = g_k + (size_t)b * KK * DD;
    const float* vb = g_v + (size_t)b * KK * DD;

    int n = blockIdx.x * 128 + t;
    bool act = n < NN;
    float* xp = g_x + ((size_t)b * NN + n) * DD;

    u64 q2[32], oh2[32];
    float l[HH];

    if (act) {
        u64 xr2[32];
        const ulonglong2* xg = (const ulonglong2*)xp;
#pragma unroll
        for (int q = 0; q < 16; q++) {
            ulonglong2 v = xg[q];
            xr2[2 * q] = v.x; xr2[2 * q + 1] = v.y;
        }
#pragma unroll
        for (int jj = 0; jj < 32; jj++) q2[jj] = 0ull;
#pragma unroll
        for (int dd = 0; dd < 32; dd++) {
            float2 xv = up2(xr2[dd]);
            {
                u64 xb = bc2(xv.x);
                const ulonglong2* wr = (const ulonglong2*)&sWq[(2 * dd) * DD];
#pragma unroll
                for (int q = 0; q < 16; q++) {
                    ulonglong2 w = wr[q];
                    q2[2 * q] = f2fma(xb, w.x, q2[2 * q]);
                    q2[2 * q + 1] = f2fma(xb, w.y, q2[2 * q + 1]);
                }
            }
            {
                u64 xb = bc2(xv.y);
                const ulonglong2* wr = (const ulonglong2*)&sWq[(2 * dd + 1) * DD];
#pragma unroll
                for (int q = 0; q < 16; q++) {
                    ulonglong2 w = wr[q];
                    q2[2 * q] = f2fma(xb, w.x, q2[2 * q]);
                    q2[2 * q + 1] = f2fma(xb, w.y, q2[2 * q + 1]);
                }
            }
        }
#pragma unroll
        for (int jj = 0; jj < 32; jj++) oh2[jj] = 0ull;
#pragma unroll
        for (int h = 0; h < HH; h++) l[h] = 0.f;
    }

    // streaming softmax over four 64-k quarters
#pragma unroll 1
    for (int pass = 0; pass < 4; pass++) {
        __syncthreads();
        for (int i = t * 4; i < 4096; i += 512) {
            *(float4*)&sK[i] = *(const float4*)&kb[pass * 4096 + i];
            *(float4*)&sV[i] = *(const float4*)&vb[pass * 4096 + i];
        }
        __syncthreads();
        if (act) {
#pragma unroll
            for (int h = 0; h < HH; h++) {
#pragma unroll 2
                for (int k = 0; k < 64; k++) {
                    const ulonglong2* kr = (const ulonglong2*)&sK[k * DD + h * DHD];
                    ulonglong2 kA = kr[0], kB = kr[1], kC = kr[2], kD = kr[3];
                    u64 c0 = f2mul(q2[h * 8 + 0], kA.x);
                    u64 c1 = f2mul(q2[h * 8 + 1], kA.y);
                    c0 = f2fma(q2[h * 8 + 2], kB.x, c0);
                    c1 = f2fma(q2[h * 8 + 3], kB.y, c1);
                    c0 = f2fma(q2[h * 8 + 4], kC.x, c0);
                    c1 = f2fma(q2[h * 8 + 5], kC.y, c1);
                    c0 = f2fma(q2[h * 8 + 6], kD.x, c0);
                    c1 = f2fma(q2[h * 8 + 7], kD.y, c1);
                    float2 sv = up2(f2add(c0, c1));
                    float p = __expf((sv.x + sv.y) * 0.25f);
                    l[h] += p;
                    u64 pb = bc2(p);
                    const ulonglong2* vr = (const ulonglong2*)&sV[k * DD + h * DHD];
                    ulonglong2 vA = vr[0], vB = vr[1], vC = vr[2], vD = vr[3];
                    oh2[h * 8 + 0] = f2fma(pb, vA.x, oh2[h * 8 + 0]);
                    oh2[h * 8 + 1] = f2fma(pb, vA.y, oh2[h * 8 + 1]);
                    oh2[h * 8 + 2] = f2fma(pb, vB.x, oh2[h * 8 + 2]);
                    oh2[h * 8 + 3] = f2fma(pb, vB.y, oh2[h * 8 + 3]);
                    oh2[h * 8 + 4] = f2fma(pb, vC.x, oh2[h * 8 + 4]);
                    oh2[h * 8 + 5] = f2fma(pb, vC.y, oh2[h * 8 + 5]);
                    oh2[h * 8 + 6] = f2fma(pb, vD.x, oh2[h * 8 + 6]);
                    oh2[h * 8 + 7] = f2fma(pb, vD.y, oh2[h * 8 + 7]);
                }
            }
        }
    }

    if (act) {
        u64 xr2[32];
        const ulonglong2* xg = (const ulonglong2*)xp;
#pragma unroll
        for (int q = 0; q < 16; q++) {
            ulonglong2 v = xg[q];
            xr2[2 * q] = v.x; xr2[2 * q + 1] = v.y;
        }
        const u64* bo2 = (const u64*)sBo;
#pragma unroll
        for (int jj = 0; jj < 32; jj++) xr2[jj] = f2add(xr2[jj], bo2[jj]);
#pragma unroll
        for (int h = 0; h < HH; h++) {
            float invl = 1.f / l[h];
#pragma unroll
            for (int jj = 0; jj < 8; jj++) {
                float2 ov = up2(oh2[h * 8 + jj]);
                {
                    u64 ob = bc2(ov.x * invl);
                    const ulonglong2* wr =
                        (const ulonglong2*)&sWo[(h * DHD + 2 * jj) * DD];
#pragma unroll
                    for (int q = 0; q < 16; q++) {
                        ulonglong2 w = wr[q];
                        xr2[2 * q] = f2fma(ob, w.x, xr2[2 * q]);
                        xr2[2 * q + 1] = f2fma(ob, w.y, xr2[2 * q + 1]);
                    }
                }
                {
                    u64 ob = bc2(ov.y * invl);
                    const ulonglong2* wr =
                        (const ulonglong2*)&sWo[(h * DHD + 2 * jj + 1) * DD];
#pragma unroll
                    for (int q = 0; q < 16; q++) {
                        ulonglong2 w = wr[q];
                        xr2[2 * q] = f2fma(ob, w.x, xr2[2 * q]);
                        xr2[2 * q + 1] = f2fma(ob, w.y, xr2[2 * q + 1]);
                    }
                }
            }
        }
        ln_store(xr2, sG, sBe, xp);
    }
}

// ---------------------------------------------------------------------------
// Fused FFN, transposed W1. grid (157, B): exact tiles, occ 3.
__global__ __launch_bounds__(128, 3) void ffn_kernel(const float* __restrict__ w1t,
                                                     const float* __restrict__ b1,
                                                     const float* __restrict__ W2,
                                                     const float* __restrict__ b2,
                                                     const float* __restrict__ g2,
                                                     const float* __restrict__ be2,
                                                     float* __restrict__ xout) {
    extern __shared__ float sm[];
    float* sW1 = sm;                  // 8192 : [128 f][64 d] f-half (transposed)
    float* sW2 = sW1 + 8192;          // 8192 : [128 f][64 d]
    float* sB1 = sW2 + 8192;          // 128
    float* sB2 = sB1 + 128;           // 64
    float* sG = sB2 + DD;             // 64
    float* sBe = sG + DD;             // 64
    int b = blockIdx.y, t = threadIdx.x;

    if (t < 16) {
        *(float4*)&sB2[t * 4] = *(const float4*)&b2[t * 4];
        *(float4*)&sG[t * 4] = *(const float4*)&g2[t * 4];
        *(float4*)&sBe[t * 4] = *(const float4*)&be2[t * 4];
    }

    int n = blockIdx.x * 128 + t;
    bool act = n < NN;
    const float* xp = g_x + ((size_t)b * NN + n) * DD;

    u64 xr2[32], facc2[32];
    if (act) {
        const ulonglong2* xg = (const ulonglong2*)xp;
#pragma unroll
        for (int q = 0; q < 16; q++) {
            ulonglong2 v = xg[q];
            xr2[2 * q] = v.x; xr2[2 * q + 1] = v.y;
        }
#pragma unroll
        for (int jj = 0; jj < 32; jj++) facc2[jj] = 0ull;
    }

#pragma unroll 1
    for (int half = 0; half < 2; half++) {
        int f0 = half * 128;
        __syncthreads();
        for (int i = t * 4; i < 8192; i += 512) {
            *(float4*)&sW1[i] = *(const float4*)&w1t[f0 * DD + i];
            *(float4*)&sW2[i] = *(const float4*)&W2[f0 * DD + i];
        }
        if (t < 32) *(float4*)&sB1[t * 4] = *(const float4*)&b1[f0 + t * 4];
        __syncthreads();

        if (act) {
            for (int fb = 0; fb < 128; fb += 8) {
                u64 hacc[8];
#pragma unroll
                for (int ff = 0; ff < 8; ff++) hacc[ff] = 0ull;
#pragma unroll
                for (int q = 0; q < 32; q += 2) {
                    u64 x0 = xr2[q], x1 = xr2[q + 1];
#pragma unroll
                    for (int ff = 0; ff < 8; ff++) {
                        ulonglong2 w =
                            *(const ulonglong2*)&sW1[(fb + ff) * DD + q * 2];
                        hacc[ff] = f2fma(x0, w.x, hacc[ff]);
                        hacc[ff] = f2fma(x1, w.y, hacc[ff]);
                    }
                }
                float hs[8];
#pragma unroll
                for (int ff = 0; ff < 8; ff++) {
                    float2 hv = up2(hacc[ff]);
                    float hval = hv.x + hv.y + sB1[fb + ff];
                    hs[ff] = 0.5f * hval *
                             (1.f + erff(hval * 0.70710678118654752440f));
                }
#pragma unroll
                for (int c = 0; c < 8; c++) {
                    u64 hb = bc2(hs[c]);
                    const ulonglong2* wr = (const ulonglong2*)&sW2[(fb + c) * DD];
#pragma unroll
                    for (int q = 0; q < 16; q++) {
                        ulonglong2 w = wr[q];
                        facc2[2 * q] = f2fma(hb, w.x, facc2[2 * q]);
                        facc2[2 * q + 1] = f2fma(hb, w.y, facc2[2 * q + 1]);
                    }
                }
            }
        }
    }

    if (act) {
        const u64* b2p = (const u64*)sB2;
#pragma unroll
        for (int jj = 0; jj < 32; jj++)
            xr2[jj] = f2add(xr2[jj], f2add(facc2[jj], b2p[jj]));
        ln_store(xr2, sG, sBe, xout + ((size_t)b * NN + n) * DD);
    }
}

// ---------------------------------------------------------------------------
extern "C" void kernel_launch(void* const* d_in, const int* in_sizes, int n_in,
                              void* d_out, int out_size) {
    const float* expr = (const float*)d_in[0];
    const float* emb = (const float*)d_in[1];
    const float* Wq = (const float*)d_in[2];
    const float* Wk = (const float*)d_in[3];
    const float* Wv = (const float*)d_in[4];
    const float* projK = (const float*)d_in[5];
    const float* projV = (const float*)d_in[6];
    const float* Wo = (const float*)d_in[7];
    const float* bo = (const float*)d_in[8];
    const float* g1 = (const float*)d_in[9];
    const float* be1 = (const float*)d_in[10];
    const float* W1 = (const float*)d_in[11];
    const float* bf1 = (const float*)d_in[12];
    const float* W2 = (const float*)d_in[13];
    const float* bf2 = (const float*)d_in[14];
    const float* g2 = (const float*)d_in[15];
    const float* be2 = (const float*)d_in[16];
    float* out = (float*)d_out;

    void* xaddr = nullptr;
    cudaGetSymbolAddress(&xaddr, g_x);
    float* gx = (float*)xaddr;
    void* w1taddr = nullptr;
    cudaGetSymbolAddress(&w1taddr, g_w1t);
    const float* gw1t = (const float*)w1taddr;

    cudaFuncSetAttribute(attn_kernel, cudaFuncAttributeMaxDynamicSharedMemorySize,
                         ATTN_SMEM_BYTES);
    cudaFuncSetAttribute(ffn_kernel, cudaFuncAttributeMaxDynamicSharedMemorySize,
                         FFN_SMEM_BYTES);

    embed_kernel<<<(BB * NN + 255) / 256, 256>>>(expr, emb);
    w1t_kernel<<<(LLAYERS * FF * DD + 255) / 256, 256>>>(W1);

    for (int l = 0; l < LLAYERS; l++) {
        proj_kernel<<<dim3(NSPLIT, BB, 2), 256>>>(projK + (size_t)l * NN * KK,
                                                  projV + (size_t)l * NN * KK);
        reduce_kernel<<<(2 * BB * KK * DD) / 256, 256>>>();
        kvproj_kernel<<<dim3(KK / 4, BB, 2), 256>>>(Wk + l * DD * DD,
                                                    Wv + l * DD * DD);
        attn_kernel<<<dim3(ATILES, BB), 128, ATTN_SMEM_BYTES>>>(
            Wq + l * DD * DD, Wo + l * DD * DD, bo + l * DD, g1 + l * DD,
            be1 + l * DD);
        ffn_kernel<<<dim3(ATILES, BB), 128, FFN_SMEM_BYTES>>>(
            gw1t + (size_t)l * FF * DD, bf1 + l * FF, W2 + (size_t)l * FF * DD,
            bf2 + l * DD, g2 + l * DD, be2 + l * DD,
            (l == LLAYERS - 1) ? out : gx);
    }
}

// round 9
// speedup vs baseline: 2.6559x; 1.5055x over previous
#include <cuda_runtime.h>
#include <cuda_bf16.h>
#include <math.h>

// Problem constants
#define BB 4
#define NN 20000
#define DD 64
#define KK 256
#define HH 4
#define DHD 16
#define FF 256
#define LLAYERS 2
#define NSPLIT 37
#define ATILES 157                   // 157*128 = 20096 >= 20000

// attn smem (unchanged from R8)
#define ATTN_SMEM_FLOATS (4096 + 4096 + 4096 + 4096 + 64 + 64 + 64)
#define ATTN_SMEM_BYTES (ATTN_SMEM_FLOATS * 4)                        // 66304
// ffn mma smem: H[128][72]u + W1[64][72]u + W2[64][72]u + b1 256 + b2/g/be 192
#define FFN_SMEM_WORDS (128 * 72 + 64 * 72 + 64 * 72 + 256 + 64 + 64 + 64)
#define FFN_SMEM_BYTES (FFN_SMEM_WORDS * 4)                           // 75520

typedef unsigned long long u64;
typedef unsigned int u32;

__device__ __forceinline__ u64 pk2(float a, float b) {
    u64 r; asm("mov.b64 %0,{%1,%2};" : "=l"(r) : "f"(a), "f"(b)); return r;
}
__device__ __forceinline__ u64 bc2(float a) { return pk2(a, a); }
__device__ __forceinline__ float2 up2(u64 v) {
    float2 r; asm("mov.b64 {%0,%1},%2;" : "=f"(r.x), "=f"(r.y) : "l"(v)); return r;
}
__device__ __forceinline__ u64 f2fma(u64 a, u64 b, u64 c) {
    u64 d; asm("fma.rn.f32x2 %0,%1,%2,%3;" : "=l"(d) : "l"(a), "l"(b), "l"(c)); return d;
}
__device__ __forceinline__ u64 f2add(u64 a, u64 b) {
    u64 d; asm("add.rn.f32x2 %0,%1,%2;" : "=l"(d) : "l"(a), "l"(b)); return d;
}
__device__ __forceinline__ u64 f2mul(u64 a, u64 b) {
    u64 d; asm("mul.rn.f32x2 %0,%1,%2;" : "=l"(d) : "l"(a), "l"(b)); return d;
}

// tf32 helpers
__device__ __forceinline__ u32 tf32c(float v) {
    u32 r; asm("cvt.rna.tf32.f32 %0,%1;" : "=r"(r) : "f"(v)); return r;
}
__device__ __forceinline__ void mma8(float4& c, u32 a0, u32 a1, u32 a2, u32 a3,
                                     u32 b0, u32 b1) {
    asm("mma.sync.aligned.m16n8k8.row.col.f32.tf32.tf32.f32 "
        "{%0,%1,%2,%3},{%4,%5,%6,%7},{%8,%9},{%0,%1,%2,%3};"
        : "+f"(c.x), "+f"(c.y), "+f"(c.z), "+f"(c.w)
        : "r"(a0), "r"(a1), "r"(a2), "r"(a3), "r"(b0), "r"(b1));
}

// Scratch (module-scope device arrays; no runtime allocation)
__device__ float g_x[BB * NN * DD];                 // activations  [B,N,D]
__device__ float g_part[NSPLIT * 2 * BB * KK * DD]; // split-N partials
__device__ float g_kvlow[2 * BB * KK * DD];         // reduced k_low / v_low
__device__ float g_k[BB * KK * DD];                 // k = k_low @ Wk
__device__ float g_v[BB * KK * DD];                 // v = v_low @ Wv

// ---------------------------------------------------------------------------
// x[b,n,d] = emb[n,d] * expr[b,n]
__global__ void embed_kernel(const float* __restrict__ expr,
                             const float* __restrict__ emb) {
    int idx = blockIdx.x * blockDim.x + threadIdx.x;
    if (idx >= BB * NN) return;
    int b = idx / NN, n = idx % NN;
    float e = expr[b * NN + n];
    const float4* er = (const float4*)&emb[(size_t)n * DD];
    float4* xo = (float4*)&g_x[(size_t)idx * DD];
#pragma unroll
    for (int i = 0; i < DD / 4; i++) {
        float4 v = er[i];
        v.x *= e; v.y *= e; v.z *= e; v.w *= e;
        xo[i] = v;
    }
}

// ---------------------------------------------------------------------------
// Split-N low-rank projection with tf32 mma.sync:
//   part[s,mat,b, k(0..255), d(0..63)] = sum_{n in chunk} P[n,k] * x[b,n,d]
// GEMM view: M=k(256), N=d(64), K=n. 8 warps, warp owns 32 M-rows.
__global__ __launch_bounds__(256) void proj_mma_kernel(const float* __restrict__ PK,
                                                       const float* __restrict__ PV) {
    __shared__ u32 sPu[16 * 264];   // A: [n-row 16][k col 256 pad 264] tf32
    __shared__ u32 sXu[16 * 72];    // B: [n-row 16][d col 64 pad 72] tf32
    int s = blockIdx.x, b = blockIdx.y, mat = blockIdx.z;
    const float* P = (mat == 0) ? PK : PV;
    int t = threadIdx.x;
    int w = t >> 5, L = t & 31, g = L >> 2, t4 = L & 3;

    float4 C[2][8];
#pragma unroll
    for (int i = 0; i < 2; i++)
#pragma unroll
        for (int j = 0; j < 8; j++) C[i][j] = make_float4(0.f, 0.f, 0.f, 0.f);

    int n0 = (s * NN) / NSPLIT;
    int n1 = ((s + 1) * NN) / NSPLIT;

    for (int n = n0; n < n1; n += 16) {
        __syncthreads();
        // stage P chunk [16][256] -> tf32
#pragma unroll
        for (int j = 0; j < 4; j++) {
            int e = (t + j * 256) * 4;
            int row = e >> 8, col = e & 255;
            int nr = n + row;
            uint4 u;
            if (nr < n1) {
                float4 v = *(const float4*)&P[(size_t)nr * KK + col];
                u.x = tf32c(v.x); u.y = tf32c(v.y); u.z = tf32c(v.z); u.w = tf32c(v.w);
            } else u = make_uint4(0, 0, 0, 0);
            *(uint4*)&sPu[row * 264 + col] = u;
        }
        {   // stage X chunk [16][64] -> tf32
            int e = t * 4;
            int row = e >> 6, col = e & 63;
            int nr = n + row;
            uint4 u;
            if (nr < n1) {
                float4 v = *(const float4*)&g_x[((size_t)b * NN + nr) * DD + col];
                u.x = tf32c(v.x); u.y = tf32c(v.y); u.z = tf32c(v.z); u.w = tf32c(v.w);
            } else u = make_uint4(0, 0, 0, 0);
            *(uint4*)&sXu[row * 72 + col] = u;
        }
        __syncthreads();

#pragma unroll
        for (int ks = 0; ks < 2; ks++) {
            int kr0 = (ks * 8 + t4) * 264;
            int kr1 = (ks * 8 + t4 + 4) * 264;
            u32 a[2][4];
#pragma unroll
            for (int mt = 0; mt < 2; mt++) {
                int m0 = w * 32 + mt * 16;
                a[mt][0] = sPu[kr0 + m0 + g];
                a[mt][1] = sPu[kr0 + m0 + g + 8];
                a[mt][2] = sPu[kr1 + m0 + g];
                a[mt][3] = sPu[kr1 + m0 + g + 8];
            }
            int xr0 = (ks * 8 + t4) * 72;
            int xr1 = (ks * 8 + t4 + 4) * 72;
#pragma unroll
            for (int nb = 0; nb < 8; nb++) {
                u32 b0 = sXu[xr0 + nb * 8 + g];
                u32 b1 = sXu[xr1 + nb * 8 + g];
                mma8(C[0][nb], a[0][0], a[0][1], a[0][2], a[0][3], b0, b1);
                mma8(C[1][nb], a[1][0], a[1][1], a[1][2], a[1][3], b0, b1);
            }
        }
    }

    float* o = g_part + (((size_t)s * 2 + mat) * BB + b) * (KK * DD);
#pragma unroll
    for (int mt = 0; mt < 2; mt++) {
        int m0 = w * 32 + mt * 16;
#pragma unroll
        for (int nb = 0; nb < 8; nb++) {
            int col = nb * 8 + 2 * t4;
            *(float2*)&o[(m0 + g) * DD + col] = make_float2(C[mt][nb].x, C[mt][nb].y);
            *(float2*)&o[(m0 + g + 8) * DD + col] = make_float2(C[mt][nb].z, C[mt][nb].w);
        }
    }
}

// ---------------------------------------------------------------------------
__global__ void reduce_kernel() {
    int idx = blockIdx.x * blockDim.x + threadIdx.x;
    if (idx >= 2 * BB * KK * DD) return;
    float sum = 0.f;
    for (int s = 0; s < NSPLIT; s++)
        sum += g_part[(size_t)s * (2 * BB * KK * DD) + idx];
    g_kvlow[idx] = sum;
}

// ---------------------------------------------------------------------------
__global__ void kvproj_kernel(const float* __restrict__ Wk,
                              const float* __restrict__ Wv) {
    int mat = blockIdx.z, b = blockIdx.y;
    const float* W = (mat == 0) ? Wk : Wv;
    __shared__ float sW[DD * DD];
    __shared__ float sL[4][DD];
    int t = threadIdx.x;
    for (int i = t * 4; i < DD * DD; i += 1024)
        *(float4*)&sW[i] = *(const float4*)&W[i];
    if (t < 64) {
        int r = t >> 4, c = (t & 15) * 4;
        int k = blockIdx.x * 4 + r;
        *(float4*)&sL[r][c] =
            *(const float4*)&g_kvlow[((size_t)mat * BB + b) * KK * DD + k * DD + c];
    }
    __syncthreads();
    int e = t & 63, kr = t >> 6;
    int k = blockIdx.x * 4 + kr;
    float sacc = 0.f;
#pragma unroll
    for (int d = 0; d < DD; d++) sacc += sL[kr][d] * sW[d * DD + e];
    float* out = (mat == 0) ? g_k : g_v;
    out[(size_t)b * KK * DD + k * DD + e] = sacc;
}

// ---------------------------------------------------------------------------
__device__ __forceinline__ void ln_store(u64* xr2, const float* sG,
                                         const float* sBe, float* op) {
    float xs[DD];
#pragma unroll
    for (int jj = 0; jj < 32; jj++) {
        float2 v = up2(xr2[jj]);
        xs[2 * jj] = v.x; xs[2 * jj + 1] = v.y;
    }
    float m = 0.f;
#pragma unroll
    for (int d = 0; d < DD; d++) m += xs[d];
    m *= (1.f / DD);
    float var = 0.f;
#pragma unroll
    for (int d = 0; d < DD; d++) { float df = xs[d] - m; var += df * df; }
    var *= (1.f / DD);
    float inv = rsqrtf(var + 1e-5f);
#pragma unroll
    for (int i = 0; i < DD; i += 4) {
        float4 o4;
        o4.x = (xs[i] - m) * inv * sG[i] + sBe[i];
        o4.y = (xs[i + 1] - m) * inv * sG[i + 1] + sBe[i + 1];
        o4.z = (xs[i + 2] - m) * inv * sG[i + 2] + sBe[i + 2];
        o4.w = (xs[i + 3] - m) * inv * sG[i + 3] + sBe[i + 3];
        *(float4*)&op[i] = o4;
    }
}

// ---------------------------------------------------------------------------
// Fused attention (unchanged from R8): exact 128-row tiles, occ 3.
__global__ __launch_bounds__(128, 3) void attn_kernel(const float* __restrict__ Wq,
                                                      const float* __restrict__ Wo,
                                                      const float* __restrict__ bo,
                                                      const float* __restrict__ g1,
                                                      const float* __restrict__ be1) {
    extern __shared__ float sm[];
    float* sK = sm;                   // 4096 (current 64-k quarter)
    float* sV = sK + 4096;            // 4096
    float* sWq = sV + 4096;           // 4096
    float* sWo = sWq + 4096;          // 4096
    float* sBo = sWo + 4096;          // 64
    float* sG = sBo + DD;             // 64
    float* sBe = sG + DD;             // 64
    int b = blockIdx.y, t = threadIdx.x;

    for (int i = t * 4; i < DD * DD; i += 512) {
        *(float4*)&sWq[i] = *(const float4*)&Wq[i];
        *(float4*)&sWo[i] = *(const float4*)&Wo[i];
    }
    if (t < 16) {
        *(float4*)&sBo[t * 4] = *(const float4*)&bo[t * 4];
        *(float4*)&sG[t * 4] = *(const float4*)&g1[t * 4];
        *(float4*)&sBe[t * 4] = *(const float4*)&be1[t * 4];
    }
    const float* kb = g_k + (size_t)b * KK * DD;
    const float* vb = g_v + (size_t)b * KK * DD;

    int n = blockIdx.x * 128 + t;
    bool act = n < NN;
    float* xp = g_x + ((size_t)b * NN + n) * DD;

    u64 q2[32], oh2[32];
    float l[HH];

    if (act) {
        u64 xr2[32];
        const ulonglong2* xg = (const ulonglong2*)xp;
#pragma unroll
        for (int q = 0; q < 16; q++) {
            ulonglong2 v = xg[q];
            xr2[2 * q] = v.x; xr2[2 * q + 1] = v.y;
        }
#pragma unroll
        for (int jj = 0; jj < 32; jj++) q2[jj] = 0ull;
#pragma unroll
        for (int dd = 0; dd < 32; dd++) {
            float2 xv = up2(xr2[dd]);
            {
                u64 xb = bc2(xv.x);
                const ulonglong2* wr = (const ulonglong2*)&sWq[(2 * dd) * DD];
#pragma unroll
                for (int q = 0; q < 16; q++) {
                    ulonglong2 w = wr[q];
                    q2[2 * q] = f2fma(xb, w.x, q2[2 * q]);
                    q2[2 * q + 1] = f2fma(xb, w.y, q2[2 * q + 1]);
                }
            }
            {
                u64 xb = bc2(xv.y);
                const ulonglong2* wr = (const ulonglong2*)&sWq[(2 * dd + 1) * DD];
#pragma unroll
                for (int q = 0; q < 16; q++) {
                    ulonglong2 w = wr[q];
                    q2[2 * q] = f2fma(xb, w.x, q2[2 * q]);
                    q2[2 * q + 1] = f2fma(xb, w.y, q2[2 * q + 1]);
                }
            }
        }
#pragma unroll
        for (int jj = 0; jj < 32; jj++) oh2[jj] = 0ull;
#pragma unroll
        for (int h = 0; h < HH; h++) l[h] = 0.f;
    }

#pragma unroll 1
    for (int pass = 0; pass < 4; pass++) {
        __syncthreads();
        for (int i = t * 4; i < 4096; i += 512) {
            *(float4*)&sK[i] = *(const float4*)&kb[pass * 4096 + i];
            *(float4*)&sV[i] = *(const float4*)&vb[pass * 4096 + i];
        }
        __syncthreads();
        if (act) {
#pragma unroll
            for (int h = 0; h < HH; h++) {
#pragma unroll 2
                for (int k = 0; k < 64; k++) {
                    const ulonglong2* kr = (const ulonglong2*)&sK[k * DD + h * DHD];
                    ulonglong2 kA = kr[0], kB = kr[1], kC = kr[2], kD = kr[3];
                    u64 c0 = f2mul(q2[h * 8 + 0], kA.x);
                    u64 c1 = f2mul(q2[h * 8 + 1], kA.y);
                    c0 = f2fma(q2[h * 8 + 2], kB.x, c0);
                    c1 = f2fma(q2[h * 8 + 3], kB.y, c1);
                    c0 = f2fma(q2[h * 8 + 4], kC.x, c0);
                    c1 = f2fma(q2[h * 8 + 5], kC.y, c1);
                    c0 = f2fma(q2[h * 8 + 6], kD.x, c0);
                    c1 = f2fma(q2[h * 8 + 7], kD.y, c1);
                    float2 sv = up2(f2add(c0, c1));
                    float p = __expf((sv.x + sv.y) * 0.25f);
                    l[h] += p;
                    u64 pb = bc2(p);
                    const ulonglong2* vr = (const ulonglong2*)&sV[k * DD + h * DHD];
                    ulonglong2 vA = vr[0], vB = vr[1], vC = vr[2], vD = vr[3];
                    oh2[h * 8 + 0] = f2fma(pb, vA.x, oh2[h * 8 + 0]);
                    oh2[h * 8 + 1] = f2fma(pb, vA.y, oh2[h * 8 + 1]);
                    oh2[h * 8 + 2] = f2fma(pb, vB.x, oh2[h * 8 + 2]);
                    oh2[h * 8 + 3] = f2fma(pb, vB.y, oh2[h * 8 + 3]);
                    oh2[h * 8 + 4] = f2fma(pb, vC.x, oh2[h * 8 + 4]);
                    oh2[h * 8 + 5] = f2fma(pb, vC.y, oh2[h * 8 + 5]);
                    oh2[h * 8 + 6] = f2fma(pb, vD.x, oh2[h * 8 + 6]);
                    oh2[h * 8 + 7] = f2fma(pb, vD.y, oh2[h * 8 + 7]);
                }
            }
        }
    }

    if (act) {
        u64 xr2[32];
        const ulonglong2* xg = (const ulonglong2*)xp;
#pragma unroll
        for (int q = 0; q < 16; q++) {
            ulonglong2 v = xg[q];
            xr2[2 * q] = v.x; xr2[2 * q + 1] = v.y;
        }
        const u64* bo2 = (const u64*)sBo;
#pragma unroll
        for (int jj = 0; jj < 32; jj++) xr2[jj] = f2add(xr2[jj], bo2[jj]);
#pragma unroll
        for (int h = 0; h < HH; h++) {
            float invl = 1.f / l[h];
#pragma unroll
            for (int jj = 0; jj < 8; jj++) {
                float2 ov = up2(oh2[h * 8 + jj]);
                {
                    u64 ob = bc2(ov.x * invl);
                    const ulonglong2* wr =
                        (const ulonglong2*)&sWo[(h * DHD + 2 * jj) * DD];
#pragma unroll
                    for (int q = 0; q < 16; q++) {
                        ulonglong2 w = wr[q];
                        xr2[2 * q] = f2fma(ob, w.x, xr2[2 * q]);
                        xr2[2 * q + 1] = f2fma(ob, w.y, xr2[2 * q + 1]);
                    }
                }
                {
                    u64 ob = bc2(ov.y * invl);
                    const ulonglong2* wr =
                        (const ulonglong2*)&sWo[(h * DHD + 2 * jj + 1) * DD];
#pragma unroll
                    for (int q = 0; q < 16; q++) {
                        ulonglong2 w = wr[q];
                        xr2[2 * q] = f2fma(ob, w.x, xr2[2 * q]);
                        xr2[2 * q + 1] = f2fma(ob, w.y, xr2[2 * q + 1]);
                    }
                }
            }
        }
        ln_store(xr2, sG, sBe, xp);
    }
}

// ---------------------------------------------------------------------------
// Fused FFN with tf32 mma.sync:
//   H = gelu(X @ W1 + b1); F = H @ W2 + b2; out = LN(F + X)
// CTA = 128 rows, 256 threads (8 warps); warp owns 16 rows.
// f processed in 4 chunks of 64. H goes through smem (warp-private rows).
__global__ __launch_bounds__(256, 2) void ffn_mma_kernel(const float* __restrict__ W1,
                                                         const float* __restrict__ b1,
                                                         const float* __restrict__ W2,
                                                         const float* __restrict__ b2,
                                                         const float* __restrict__ g2,
                                                         const float* __restrict__ be2,
                                                         float* __restrict__ xout) {
    extern __shared__ u32 smu[];
    u32* sHu = smu;                       // [128][72] tf32
    u32* sW1u = sHu + 128 * 72;           // [64 d][72 f-pad] tf32
    u32* sW2u = sW1u + 64 * 72;           // [64 f][72 d-pad] tf32
    float* sB1 = (float*)(sW2u + 64 * 72);  // 256
    float* sB2 = sB1 + 256;               // 64
    float* sG = sB2 + 64;                 // 64
    float* sBe = sG + 64;                 // 64

    int b = blockIdx.y, t = threadIdx.x;
    int w = t >> 5, L = t & 31, g = L >> 2, t4 = L & 3;
    int row0 = blockIdx.x * 128;

    if (t < 64) *(float4*)&sB1[t * 4] = *(const float4*)&b1[t * 4];
    if (t < 16) {
        *(float4*)&sB2[t * 4] = *(const float4*)&b2[t * 4];
        *(float4*)&sG[t * 4] = *(const float4*)&g2[t * 4];
        *(float4*)&sBe[t * 4] = *(const float4*)&be2[t * 4];
    }

    const float* xbase = g_x + (size_t)b * NN * DD;
    int rg = row0 + w * 16 + g;          // this thread's first row
    int rg8 = rg + 8;                    // second row
    bool vg = rg < NN, vg8 = rg8 < NN;

    float4 C2[8];
#pragma unroll
    for (int nb = 0; nb < 8; nb++) C2[nb] = make_float4(0.f, 0.f, 0.f, 0.f);

#pragma unroll 1
    for (int fc = 0; fc < 4; fc++) {
        int f0 = fc * 64;
        __syncthreads();
        // stage W1 chunk [64 d][64 f] and W2 chunk [64 f][64 d] as tf32
#pragma unroll
        for (int j = 0; j < 4; j++) {
            int e = (t + j * 256) * 4;
            int r = e >> 6, c = e & 63;
            float4 v1 = *(const float4*)&W1[r * FF + f0 + c];
            uint4 u1 = make_uint4(tf32c(v1.x), tf32c(v1.y), tf32c(v1.z), tf32c(v1.w));
            *(uint4*)&sW1u[r * 72 + c] = u1;
            float4 v2 = *(const float4*)&W2[(f0 + r) * DD + c];
            uint4 u2 = make_uint4(tf32c(v2.x), tf32c(v2.y), tf32c(v2.z), tf32c(v2.w));
            *(uint4*)&sW2u[r * 72 + c] = u2;
        }
        __syncthreads();

        // GEMM1: C1[16 rows x 64 f] = X[16 x 64] @ W1chunk, bias preloaded
        float4 C1[8];
#pragma unroll
        for (int nb = 0; nb < 8; nb++) {
            int col = f0 + nb * 8 + 2 * t4;
            C1[nb] = make_float4(sB1[col], sB1[col + 1], sB1[col], sB1[col + 1]);
        }
#pragma unroll
        for (int ks = 0; ks < 8; ks++) {
            u32 a0 = tf32c(vg ? xbase[(size_t)rg * DD + ks * 8 + t4] : 0.f);
            u32 a1 = tf32c(vg8 ? xbase[(size_t)rg8 * DD + ks * 8 + t4] : 0.f);
            u32 a2 = tf32c(vg ? xbase[(size_t)rg * DD + ks * 8 + t4 + 4] : 0.f);
            u32 a3 = tf32c(vg8 ? xbase[(size_t)rg8 * DD + ks * 8 + t4 + 4] : 0.f);
            int wr0 = (ks * 8 + t4) * 72;
            int wr1 = (ks * 8 + t4 + 4) * 72;
#pragma unroll
            for (int nb = 0; nb < 8; nb++) {
                u32 b0 = sW1u[wr0 + nb * 8 + g];
                u32 b1r = sW1u[wr1 + nb * 8 + g];
                mma8(C1[nb], a0, a1, a2, a3, b0, b1r);
            }
        }
        // GELU (exact) + store H to smem as tf32
#pragma unroll
        for (int nb = 0; nb < 8; nb++) {
            float h0 = C1[nb].x, h1 = C1[nb].y, h2 = C1[nb].z, h3 = C1[nb].w;
            h0 = 0.5f * h0 * (1.f + erff(h0 * 0.70710678118654752440f));
            h1 = 0.5f * h1 * (1.f + erff(h1 * 0.70710678118654752440f));
            h2 = 0.5f * h2 * (1.f + erff(h2 * 0.70710678118654752440f));
            h3 = 0.5f * h3 * (1.f + erff(h3 * 0.70710678118654752440f));
            int col = nb * 8 + 2 * t4;
            *(uint2*)&sHu[(w * 16 + g) * 72 + col] = make_uint2(tf32c(h0), tf32c(h1));
            *(uint2*)&sHu[(w * 16 + g + 8) * 72 + col] = make_uint2(tf32c(h2), tf32c(h3));
        }
        __syncwarp();
        // GEMM2: C2[16 rows x 64 d] += H[16 x 64] @ W2chunk
#pragma unroll
        for (int ks = 0; ks < 8; ks++) {
            u32 a0 = sHu[(w * 16 + g) * 72 + ks * 8 + t4];
            u32 a1 = sHu[(w * 16 + g + 8) * 72 + ks * 8 + t4];
            u32 a2 = sHu[(w * 16 + g) * 72 + ks * 8 + t4 + 4];
            u32 a3 = sHu[(w * 16 + g + 8) * 72 + ks * 8 + t4 + 4];
            int wr0 = (ks * 8 + t4) * 72;
            int wr1 = (ks * 8 + t4 + 4) * 72;
#pragma unroll
            for (int nb = 0; nb < 8; nb++) {
                u32 b0 = sW2u[wr0 + nb * 8 + g];
                u32 b1r = sW2u[wr1 + nb * 8 + g];
                mma8(C2[nb], a0, a1, a2, a3, b0, b1r);
            }
        }
    }

    // Epilogue: +b2, +residual x, LayerNorm per row, store.
    // Thread holds cols {nb*8+2t4, +1} for rows rg (x,y) and rg8 (z,w).
    // Quad (lanes with same g) covers the full 64-col row.
#pragma unroll 1
    for (int rp = 0; rp < 2; rp++) {
        int r = rp ? rg8 : rg;
        bool vr = rp ? vg8 : vg;
        float vx[8], vy[8];
#pragma unroll
        for (int nb = 0; nb < 8; nb++) {
            int col = nb * 8 + 2 * t4;
            float2 xv = vr ? *(const float2*)&xbase[(size_t)r * DD + col]
                           : make_float2(0.f, 0.f);
            float cva = rp ? C2[nb].z : C2[nb].x;
            float cvb = rp ? C2[nb].w : C2[nb].y;
            vx[nb] = cva + sB2[col] + xv.x;
            vy[nb] = cvb + sB2[col + 1] + xv.y;
        }
        float s = 0.f;
#pragma unroll
        for (int nb = 0; nb < 8; nb++) s += vx[nb] + vy[nb];
        s += __shfl_xor_sync(0xffffffffu, s, 1);
        s += __shfl_xor_sync(0xffffffffu, s, 2);
        float m = s * (1.f / DD);
        float q = 0.f;
#pragma unroll
        for (int nb = 0; nb < 8; nb++) {
            float d0 = vx[nb] - m, d1 = vy[nb] - m;
            q += d0 * d0 + d1 * d1;
        }
        q += __shfl_xor_sync(0xffffffffu, q, 1);
        q += __shfl_xor_sync(0xffffffffu, q, 2);
        float inv = rsqrtf(q * (1.f / DD) + 1e-5f);
        if (vr) {
            float* op = xout + ((size_t)b * NN + r) * DD;
#pragma unroll
            for (int nb = 0; nb < 8; nb++) {
                int col = nb * 8 + 2 * t4;
                float2 o2;
                o2.x = (vx[nb] - m) * inv * sG[col] + sBe[col];
                o2.y = (vy[nb] - m) * inv * sG[col + 1] + sBe[col + 1];
                *(float2*)&op[col] = o2;
            }
        }
    }
}

// ---------------------------------------------------------------------------
extern "C" void kernel_launch(void* const* d_in, const int* in_sizes, int n_in,
                              void* d_out, int out_size) {
    const float* expr = (const float*)d_in[0];
    const float* emb = (const float*)d_in[1];
    const float* Wq = (const float*)d_in[2];
    const float* Wk = (const float*)d_in[3];
    const float* Wv = (const float*)d_in[4];
    const float* projK = (const float*)d_in[5];
    const float* projV = (const float*)d_in[6];
    const float* Wo = (const float*)d_in[7];
    const float* bo = (const float*)d_in[8];
    const float* g1 = (const float*)d_in[9];
    const float* be1 = (const float*)d_in[10];
    const float* W1 = (const float*)d_in[11];
    const float* bf1 = (const float*)d_in[12];
    const float* W2 = (const float*)d_in[13];
    const float* bf2 = (const float*)d_in[14];
    const float* g2 = (const float*)d_in[15];
    const float* be2 = (const float*)d_in[16];
    float* out = (float*)d_out;

    void* xaddr = nullptr;
    cudaGetSymbolAddress(&xaddr, g_x);
    float* gx = (float*)xaddr;

    cudaFuncSetAttribute(attn_kernel, cudaFuncAttributeMaxDynamicSharedMemorySize,
                         ATTN_SMEM_BYTES);
    cudaFuncSetAttribute(ffn_mma_kernel, cudaFuncAttributeMaxDynamicSharedMemorySize,
                         FFN_SMEM_BYTES);

    embed_kernel<<<(BB * NN + 255) / 256, 256>>>(expr, emb);

    for (int l = 0; l < LLAYERS; l++) {
        proj_mma_kernel<<<dim3(NSPLIT, BB, 2), 256>>>(projK + (size_t)l * NN * KK,
                                                      projV + (size_t)l * NN * KK);
        reduce_kernel<<<(2 * BB * KK * DD) / 256, 256>>>();
        kvproj_kernel<<<dim3(KK / 4, BB, 2), 256>>>(Wk + l * DD * DD,
                                                    Wv + l * DD * DD);
        attn_kernel<<<dim3(ATILES, BB), 128, ATTN_SMEM_BYTES>>>(
            Wq + l * DD * DD, Wo + l * DD * DD, bo + l * DD, g1 + l * DD,
            be1 + l * DD);
        ffn_mma_kernel<<<dim3(ATILES, BB), 256, FFN_SMEM_BYTES>>>(
            W1 + (size_t)l * DD * FF, bf1 + l * FF, W2 + (size_t)l * FF * DD,
            bf2 + l * DD, g2 + l * DD, be2 + l * DD,
            (l == LLAYERS - 1) ? out : gx);
    }
}

// round 11
// speedup vs baseline: 4.4430x; 1.6729x over previous
#include <cuda_runtime.h>
#include <cuda_bf16.h>
#include <math.h>

// Problem constants
#define BB 4
#define NN 20000
#define DD 64
#define KK 256
#define HH 4
#define DHD 16
#define FF 256
#define LLAYERS 2
#define NSPLIT 37
#define ATILES 157                   // 157*128 = 20096 >= 20000

// attn mma smem: sQ[128*72] + sP[128*72] + sC[2*64*72] + consts 192
#define ATTN_SMEM_WORDS (128 * 72 + 128 * 72 + 2 * 64 * 72 + 64 + 64 + 64)
#define ATTN_SMEM_BYTES (ATTN_SMEM_WORDS * 4)                         // 111360
// ffn mma smem: H[128][72]u + W1[64][72]u + W2[64][72]u + b1 256 + b2/g/be 192
#define FFN_SMEM_WORDS (128 * 72 + 64 * 72 + 64 * 72 + 256 + 64 + 64 + 64)
#define FFN_SMEM_BYTES (FFN_SMEM_WORDS * 4)                           // 75520

typedef unsigned long long u64;
typedef unsigned int u32;

// tf32 helpers
__device__ __forceinline__ u32 tf32c(float v) {
    u32 r; asm("cvt.rna.tf32.f32 %0,%1;" : "=r"(r) : "f"(v)); return r;
}
__device__ __forceinline__ void mma8(float4& c, u32 a0, u32 a1, u32 a2, u32 a3,
                                     u32 b0, u32 b1) {
    asm("mma.sync.aligned.m16n8k8.row.col.f32.tf32.tf32.f32 "
        "{%0,%1,%2,%3},{%4,%5,%6,%7},{%8,%9},{%0,%1,%2,%3};"
        : "+f"(c.x), "+f"(c.y), "+f"(c.z), "+f"(c.w)
        : "r"(a0), "r"(a1), "r"(a2), "r"(a3), "r"(b0), "r"(b1));
}

// Scratch (module-scope device arrays; no runtime allocation)
__device__ float g_x[BB * NN * DD];                 // activations  [B,N,D]
__device__ float g_part[NSPLIT * 2 * BB * KK * DD]; // split-N partials
__device__ float g_kvlow[2 * BB * KK * DD];         // reduced k_low / v_low
__device__ float g_k[BB * KK * DD];                 // k = k_low @ Wk   [b][k][d]
__device__ float g_kt[BB * DD * KK];                // k transposed     [b][d][k]
__device__ float g_v[BB * KK * DD];                 // v = v_low @ Wv   [b][k][d]

// ---------------------------------------------------------------------------
// x[b,n,d] = emb[n,d] * expr[b,n]
__global__ void embed_kernel(const float* __restrict__ expr,
                             const float* __restrict__ emb) {
    int idx = blockIdx.x * blockDim.x + threadIdx.x;
    if (idx >= BB * NN) return;
    int b = idx / NN, n = idx % NN;
    float e = expr[b * NN + n];
    const float4* er = (const float4*)&emb[(size_t)n * DD];
    float4* xo = (float4*)&g_x[(size_t)idx * DD];
#pragma unroll
    for (int i = 0; i < DD / 4; i++) {
        float4 v = er[i];
        v.x *= e; v.y *= e; v.z *= e; v.w *= e;
        xo[i] = v;
    }
}

// ---------------------------------------------------------------------------
// Split-N low-rank projection with tf32 mma.sync (unchanged from R9)
__global__ __launch_bounds__(256) void proj_mma_kernel(const float* __restrict__ PK,
                                                       const float* __restrict__ PV) {
    __shared__ u32 sPu[16 * 264];
    __shared__ u32 sXu[16 * 72];
    int s = blockIdx.x, b = blockIdx.y, mat = blockIdx.z;
    const float* P = (mat == 0) ? PK : PV;
    int t = threadIdx.x;
    int w = t >> 5, L = t & 31, g = L >> 2, t4 = L & 3;

    float4 C[2][8];
#pragma unroll
    for (int i = 0; i < 2; i++)
#pragma unroll
        for (int j = 0; j < 8; j++) C[i][j] = make_float4(0.f, 0.f, 0.f, 0.f);

    int n0 = (s * NN) / NSPLIT;
    int n1 = ((s + 1) * NN) / NSPLIT;

    for (int n = n0; n < n1; n += 16) {
        __syncthreads();
#pragma unroll
        for (int j = 0; j < 4; j++) {
            int e = (t + j * 256) * 4;
            int row = e >> 8, col = e & 255;
            int nr = n + row;
            uint4 u;
            if (nr < n1) {
                float4 v = *(const float4*)&P[(size_t)nr * KK + col];
                u.x = tf32c(v.x); u.y = tf32c(v.y); u.z = tf32c(v.z); u.w = tf32c(v.w);
            } else u = make_uint4(0, 0, 0, 0);
            *(uint4*)&sPu[row * 264 + col] = u;
        }
        {
            int e = t * 4;
            int row = e >> 6, col = e & 63;
            int nr = n + row;
            uint4 u;
            if (nr < n1) {
                float4 v = *(const float4*)&g_x[((size_t)b * NN + nr) * DD + col];
                u.x = tf32c(v.x); u.y = tf32c(v.y); u.z = tf32c(v.z); u.w = tf32c(v.w);
            } else u = make_uint4(0, 0, 0, 0);
            *(uint4*)&sXu[row * 72 + col] = u;
        }
        __syncthreads();

#pragma unroll
        for (int ks = 0; ks < 2; ks++) {
            int kr0 = (ks * 8 + t4) * 264;
            int kr1 = (ks * 8 + t4 + 4) * 264;
            u32 a[2][4];
#pragma unroll
            for (int mt = 0; mt < 2; mt++) {
                int m0 = w * 32 + mt * 16;
                a[mt][0] = sPu[kr0 + m0 + g];
                a[mt][1] = sPu[kr0 + m0 + g + 8];
                a[mt][2] = sPu[kr1 + m0 + g];
                a[mt][3] = sPu[kr1 + m0 + g + 8];
            }
            int xr0 = (ks * 8 + t4) * 72;
            int xr1 = (ks * 8 + t4 + 4) * 72;
#pragma unroll
            for (int nb = 0; nb < 8; nb++) {
                u32 b0 = sXu[xr0 + nb * 8 + g];
                u32 b1 = sXu[xr1 + nb * 8 + g];
                mma8(C[0][nb], a[0][0], a[0][1], a[0][2], a[0][3], b0, b1);
                mma8(C[1][nb], a[1][0], a[1][1], a[1][2], a[1][3], b0, b1);
            }
        }
    }

    float* o = g_part + (((size_t)s * 2 + mat) * BB + b) * (KK * DD);
#pragma unroll
    for (int mt = 0; mt < 2; mt++) {
        int m0 = w * 32 + mt * 16;
#pragma unroll
        for (int nb = 0; nb < 8; nb++) {
            int col = nb * 8 + 2 * t4;
            *(float2*)&o[(m0 + g) * DD + col] = make_float2(C[mt][nb].x, C[mt][nb].y);
            *(float2*)&o[(m0 + g + 8) * DD + col] = make_float2(C[mt][nb].z, C[mt][nb].w);
        }
    }
}

// ---------------------------------------------------------------------------
__global__ void reduce_kernel() {
    int idx = blockIdx.x * blockDim.x + threadIdx.x;
    if (idx >= 2 * BB * KK * DD) return;
    float sum = 0.f;
    for (int s = 0; s < NSPLIT; s++)
        sum += g_part[(size_t)s * (2 * BB * KK * DD) + idx];
    g_kvlow[idx] = sum;
}

// ---------------------------------------------------------------------------
// k/v head projections; also writes K transposed for the attention MMA.
__global__ void kvproj_kernel(const float* __restrict__ Wk,
                              const float* __restrict__ Wv) {
    int mat = blockIdx.z, b = blockIdx.y;
    const float* W = (mat == 0) ? Wk : Wv;
    __shared__ float sW[DD * DD];
    __shared__ float sL[4][DD];
    int t = threadIdx.x;
    for (int i = t * 4; i < DD * DD; i += 1024)
        *(float4*)&sW[i] = *(const float4*)&W[i];
    if (t < 64) {
        int r = t >> 4, c = (t & 15) * 4;
        int k = blockIdx.x * 4 + r;
        *(float4*)&sL[r][c] =
            *(const float4*)&g_kvlow[((size_t)mat * BB + b) * KK * DD + k * DD + c];
    }
    __syncthreads();
    int e = t & 63, kr = t >> 6;
    int k = blockIdx.x * 4 + kr;
    float sacc = 0.f;
#pragma unroll
    for (int d = 0; d < DD; d++) sacc += sL[kr][d] * sW[d * DD + e];
    if (mat == 0) {
        g_k[(size_t)b * KK * DD + k * DD + e] = sacc;
        g_kt[((size_t)b * DD + e) * KK + k] = sacc;
    } else {
        g_v[(size_t)b * KK * DD + k * DD + e] = sacc;
    }
}

// ---------------------------------------------------------------------------
// Fused attention with tf32 mma.sync:
//   Q = X@Wq; S_h = Q_h @ K_h^T; P = exp(S/4); O_h = P_h @ V_h / l;
//   out = LN(O @ Wo + bo + X)
// CTA = 128 rows, 256 threads (8 warps, warp = 16 rows). K in 4 chunks of 64.
__global__ __launch_bounds__(256, 2) void attn_mma_kernel(const float* __restrict__ Wq,
                                                          const float* __restrict__ Wo,
                                                          const float* __restrict__ bo,
                                                          const float* __restrict__ g1,
                                                          const float* __restrict__ be1) {
    extern __shared__ u32 smu[];
    u32* sQ = smu;                        // [128][72] tf32
    u32* sP = sQ + 128 * 72;              // [128][72] tf32 (P, later O)
    u32* sC = sP + 128 * 72;              // [2][64][72]: Wq | (KT,V) | Wo
    float* sBo = (float*)(sC + 2 * 64 * 72);
    float* sG = sBo + 64;
    float* sBe = sG + 64;

    int b = blockIdx.y, t = threadIdx.x;
    int w = t >> 5, L = t & 31, g = L >> 2, t4 = L & 3;
    int row0 = blockIdx.x * 128;
    int rg = row0 + w * 16 + g;
    int rg8 = rg + 8;
    bool vg = rg < NN, vg8 = rg8 < NN;
    const float* xbase = g_x + (size_t)b * NN * DD;
    int rq = w * 16 + g;                  // local row of this thread (first)

    if (t < 16) {
        *(float4*)&sBo[t * 4] = *(const float4*)&bo[t * 4];
        *(float4*)&sG[t * 4] = *(const float4*)&g1[t * 4];
        *(float4*)&sBe[t * 4] = *(const float4*)&be1[t * 4];
    }
    // stage Wq [64 d][64 e] tf32 into sC[0]
#pragma unroll
    for (int j = 0; j < 4; j++) {
        int e = (t + j * 256) * 4;
        int r = e >> 6, c = e & 63;
        float4 v = *(const float4*)&Wq[r * DD + c];
        *(uint4*)&sC[r * 72 + c] =
            make_uint4(tf32c(v.x), tf32c(v.y), tf32c(v.z), tf32c(v.w));
    }
    __syncthreads();

    // Q = X @ Wq
    {
        float4 CQ[8];
#pragma unroll
        for (int nb = 0; nb < 8; nb++) CQ[nb] = make_float4(0.f, 0.f, 0.f, 0.f);
#pragma unroll
        for (int ks = 0; ks < 8; ks++) {
            u32 a0 = tf32c(vg ? xbase[(size_t)rg * DD + ks * 8 + t4] : 0.f);
            u32 a1 = tf32c(vg8 ? xbase[(size_t)rg8 * DD + ks * 8 + t4] : 0.f);
            u32 a2 = tf32c(vg ? xbase[(size_t)rg * DD + ks * 8 + t4 + 4] : 0.f);
            u32 a3 = tf32c(vg8 ? xbase[(size_t)rg8 * DD + ks * 8 + t4 + 4] : 0.f);
            int wr0 = (ks * 8 + t4) * 72;
            int wr1 = (ks * 8 + t4 + 4) * 72;
#pragma unroll
            for (int nb = 0; nb < 8; nb++) {
                u32 b0 = sC[wr0 + nb * 8 + g];
                u32 b1 = sC[wr1 + nb * 8 + g];
                mma8(CQ[nb], a0, a1, a2, a3, b0, b1);
            }
        }
#pragma unroll
        for (int nb = 0; nb < 8; nb++) {
            int col = nb * 8 + 2 * t4;
            *(uint2*)&sQ[rq * 72 + col] = make_uint2(tf32c(CQ[nb].x), tf32c(CQ[nb].y));
            *(uint2*)&sQ[(rq + 8) * 72 + col] =
                make_uint2(tf32c(CQ[nb].z), tf32c(CQ[nb].w));
        }
    }

    const float* ktb = g_kt + (size_t)b * DD * KK;   // [d][256]
    const float* vb = g_v + (size_t)b * KK * DD;     // [k][64]

    float lx[HH], lz[HH];
    float4 O[HH][2];
#pragma unroll
    for (int h = 0; h < HH; h++) {
        lx[h] = 0.f; lz[h] = 0.f;
        O[h][0] = make_float4(0.f, 0.f, 0.f, 0.f);
        O[h][1] = make_float4(0.f, 0.f, 0.f, 0.f);
    }

#pragma unroll 1
    for (int chunk = 0; chunk < 4; chunk++) {
        int k0 = chunk * 64;
        __syncthreads();   // prior reads of sC (and qproj's) complete
        // stage KT chunk [64 d][64 k] and V chunk [64 k][64 d] tf32
#pragma unroll
        for (int j = 0; j < 4; j++) {
            int e = (t + j * 256) * 4;
            int r = e >> 6, c = e & 63;
            float4 kv = *(const float4*)&ktb[(size_t)r * KK + k0 + c];
            *(uint4*)&sC[r * 72 + c] =
                make_uint4(tf32c(kv.x), tf32c(kv.y), tf32c(kv.z), tf32c(kv.w));
            float4 vv = *(const float4*)&vb[(size_t)(k0 + r) * DD + c];
            *(uint4*)&sC[64 * 72 + r * 72 + c] =
                make_uint4(tf32c(vv.x), tf32c(vv.y), tf32c(vv.z), tf32c(vv.w));
        }
        __syncthreads();

#pragma unroll
        for (int h = 0; h < HH; h++) {
            // S_h = Q_h @ KT_h  (M=16/warp, N=64, Kred=16)
            float4 CS[8];
#pragma unroll
            for (int nb = 0; nb < 8; nb++) CS[nb] = make_float4(0.f, 0.f, 0.f, 0.f);
#pragma unroll
            for (int ks = 0; ks < 2; ks++) {
                int kd = h * 16 + ks * 8;
                u32 a0 = sQ[rq * 72 + kd + t4];
                u32 a1 = sQ[(rq + 8) * 72 + kd + t4];
                u32 a2 = sQ[rq * 72 + kd + t4 + 4];
                u32 a3 = sQ[(rq + 8) * 72 + kd + t4 + 4];
                int wr0 = (kd + t4) * 72;
                int wr1 = (kd + t4 + 4) * 72;
#pragma unroll
                for (int nb = 0; nb < 8; nb++) {
                    u32 b0 = sC[wr0 + nb * 8 + g];
                    u32 b1 = sC[wr1 + nb * 8 + g];
                    mma8(CS[nb], a0, a1, a2, a3, b0, b1);
                }
            }
            // exp, accumulate l, store P (warp-private rows)
#pragma unroll
            for (int nb = 0; nb < 8; nb++) {
                float px = __expf(CS[nb].x * 0.25f);
                float py = __expf(CS[nb].y * 0.25f);
                float pz = __expf(CS[nb].z * 0.25f);
                float pw = __expf(CS[nb].w * 0.25f);
                lx[h] += px + py;
                lz[h] += pz + pw;
                int col = nb * 8 + 2 * t4;
                *(uint2*)&sP[rq * 72 + col] = make_uint2(tf32c(px), tf32c(py));
                *(uint2*)&sP[(rq + 8) * 72 + col] = make_uint2(tf32c(pz), tf32c(pw));
            }
            __syncwarp();
            // O_h += P @ V_h  (N=16 -> 2 nb, Kred=64 -> 8 ks)
#pragma unroll
            for (int ks = 0; ks < 8; ks++) {
                u32 a0 = sP[rq * 72 + ks * 8 + t4];
                u32 a1 = sP[(rq + 8) * 72 + ks * 8 + t4];
                u32 a2 = sP[rq * 72 + ks * 8 + t4 + 4];
                u32 a3 = sP[(rq + 8) * 72 + ks * 8 + t4 + 4];
                int vr0 = 64 * 72 + (ks * 8 + t4) * 72;
                int vr1 = 64 * 72 + (ks * 8 + t4 + 4) * 72;
#pragma unroll
                for (int nb = 0; nb < 2; nb++) {
                    u32 b0 = sC[vr0 + h * 16 + nb * 8 + g];
                    u32 b1 = sC[vr1 + h * 16 + nb * 8 + g];
                    mma8(O[h][nb], a0, a1, a2, a3, b0, b1);
                }
            }
            __syncwarp();   // before next head overwrites sP
        }
    }

    // reduce l across quad (lanes t4 0..3 share rows)
#pragma unroll
    for (int h = 0; h < HH; h++) {
        lx[h] += __shfl_xor_sync(0xffffffffu, lx[h], 1);
        lx[h] += __shfl_xor_sync(0xffffffffu, lx[h], 2);
        lz[h] += __shfl_xor_sync(0xffffffffu, lz[h], 1);
        lz[h] += __shfl_xor_sync(0xffffffffu, lz[h], 2);
    }
    // normalized O -> sP (as tf32): cols h*16 + nb*8 + 2t4
#pragma unroll
    for (int h = 0; h < HH; h++) {
        float ix = 1.f / lx[h], iz = 1.f / lz[h];
#pragma unroll
        for (int nb = 0; nb < 2; nb++) {
            int col = h * 16 + nb * 8 + 2 * t4;
            *(uint2*)&sP[rq * 72 + col] =
                make_uint2(tf32c(O[h][nb].x * ix), tf32c(O[h][nb].y * ix));
            *(uint2*)&sP[(rq + 8) * 72 + col] =
                make_uint2(tf32c(O[h][nb].z * iz), tf32c(O[h][nb].w * iz));
        }
    }
    __syncthreads();
    // stage Wo [64][64] tf32 into sC[0]
#pragma unroll
    for (int j = 0; j < 4; j++) {
        int e = (t + j * 256) * 4;
        int r = e >> 6, c = e & 63;
        float4 v = *(const float4*)&Wo[r * DD + c];
        *(uint4*)&sC[r * 72 + c] =
            make_uint4(tf32c(v.x), tf32c(v.y), tf32c(v.z), tf32c(v.w));
    }
    __syncthreads();

    // C2 = O @ Wo
    float4 C2[8];
#pragma unroll
    for (int nb = 0; nb < 8; nb++) C2[nb] = make_float4(0.f, 0.f, 0.f, 0.f);
#pragma unroll
    for (int ks = 0; ks < 8; ks++) {
        u32 a0 = sP[rq * 72 + ks * 8 + t4];
        u32 a1 = sP[(rq + 8) * 72 + ks * 8 + t4];
        u32 a2 = sP[rq * 72 + ks * 8 + t4 + 4];
        u32 a3 = sP[(rq + 8) * 72 + ks * 8 + t4 + 4];
        int wr0 = (ks * 8 + t4) * 72;
        int wr1 = (ks * 8 + t4 + 4) * 72;
#pragma unroll
        for (int nb = 0; nb < 8; nb++) {
            u32 b0 = sC[wr0 + nb * 8 + g];
            u32 b1 = sC[wr1 + nb * 8 + g];
            mma8(C2[nb], a0, a1, a2, a3, b0, b1);
        }
    }

    // Epilogue: +bo, +residual x, LayerNorm, store to g_x (in place)
#pragma unroll 1
    for (int rp = 0; rp < 2; rp++) {
        int r = rp ? rg8 : rg;
        bool vr = rp ? vg8 : vg;
        float vx[8], vy[8];
#pragma unroll
        for (int nb = 0; nb < 8; nb++) {
            int col = nb * 8 + 2 * t4;
            float2 xv = vr ? *(const float2*)&xbase[(size_t)r * DD + col]
                           : make_float2(0.f, 0.f);
            float cva = rp ? C2[nb].z : C2[nb].x;
            float cvb = rp ? C2[nb].w : C2[nb].y;
            vx[nb] = cva + sBo[col] + xv.x;
            vy[nb] = cvb + sBo[col + 1] + xv.y;
        }
        float s = 0.f;
#pragma unroll
        for (int nb = 0; nb < 8; nb++) s += vx[nb] + vy[nb];
        s += __shfl_xor_sync(0xffffffffu, s, 1);
        s += __shfl_xor_sync(0xffffffffu, s, 2);
        float m = s * (1.f / DD);
        float q = 0.f;
#pragma unroll
        for (int nb = 0; nb < 8; nb++) {
            float d0 = vx[nb] - m, d1 = vy[nb] - m;
            q += d0 * d0 + d1 * d1;
        }
        q += __shfl_xor_sync(0xffffffffu, q, 1);
        q += __shfl_xor_sync(0xffffffffu, q, 2);
        float inv = rsqrtf(q * (1.f / DD) + 1e-5f);
        if (vr) {
            float* op = g_x + ((size_t)b * NN + r) * DD;
#pragma unroll
            for (int nb = 0; nb < 8; nb++) {
                int col = nb * 8 + 2 * t4;
                float2 o2;
                o2.x = (vx[nb] - m) * inv * sG[col] + sBe[col];
                o2.y = (vy[nb] - m) * inv * sG[col + 1] + sBe[col + 1];
                *(float2*)&op[col] = o2;
            }
        }
    }
}

// ---------------------------------------------------------------------------
// Fused FFN with tf32 mma.sync (unchanged from R9)
__global__ __launch_bounds__(256, 2) void ffn_mma_kernel(const float* __restrict__ W1,
                                                         const float* __restrict__ b1,
                                                         const float* __restrict__ W2,
                                                         const float* __restrict__ b2,
                                                         const float* __restrict__ g2,
                                                         const float* __restrict__ be2,
                                                         float* __restrict__ xout) {
    extern __shared__ u32 smu[];
    u32* sHu = smu;
    u32* sW1u = sHu + 128 * 72;
    u32* sW2u = sW1u + 64 * 72;
    float* sB1 = (float*)(sW2u + 64 * 72);
    float* sB2 = sB1 + 256;
    float* sG = sB2 + 64;
    float* sBe = sG + 64;

    int b = blockIdx.y, t = threadIdx.x;
    int w = t >> 5, L = t & 31, g = L >> 2, t4 = L & 3;
    int row0 = blockIdx.x * 128;

    if (t < 64) *(float4*)&sB1[t * 4] = *(const float4*)&b1[t * 4];
    if (t < 16) {
        *(float4*)&sB2[t * 4] = *(const float4*)&b2[t * 4];
        *(float4*)&sG[t * 4] = *(const float4*)&g2[t * 4];
        *(float4*)&sBe[t * 4] = *(const float4*)&be2[t * 4];
    }

    const float* xbase = g_x + (size_t)b * NN * DD;
    int rg = row0 + w * 16 + g;
    int rg8 = rg + 8;
    bool vg = rg < NN, vg8 = rg8 < NN;

    float4 C2[8];
#pragma unroll
    for (int nb = 0; nb < 8; nb++) C2[nb] = make_float4(0.f, 0.f, 0.f, 0.f);

#pragma unroll 1
    for (int fc = 0; fc < 4; fc++) {
        int f0 = fc * 64;
        __syncthreads();
#pragma unroll
        for (int j = 0; j < 4; j++) {
            int e = (t + j * 256) * 4;
            int r = e >> 6, c = e & 63;
            float4 v1 = *(const float4*)&W1[r * FF + f0 + c];
            *(uint4*)&sW1u[r * 72 + c] =
                make_uint4(tf32c(v1.x), tf32c(v1.y), tf32c(v1.z), tf32c(v1.w));
            float4 v2 = *(const float4*)&W2[(f0 + r) * DD + c];
            *(uint4*)&sW2u[r * 72 + c] =
                make_uint4(tf32c(v2.x), tf32c(v2.y), tf32c(v2.z), tf32c(v2.w));
        }
        __syncthreads();

        float4 C1[8];
#pragma unroll
        for (int nb = 0; nb < 8; nb++) {
            int col = f0 + nb * 8 + 2 * t4;
            C1[nb] = make_float4(sB1[col], sB1[col + 1], sB1[col], sB1[col + 1]);
        }
#pragma unroll
        for (int ks = 0; ks < 8; ks++) {
            u32 a0 = tf32c(vg ? xbase[(size_t)rg * DD + ks * 8 + t4] : 0.f);
            u32 a1 = tf32c(vg8 ? xbase[(size_t)rg8 * DD + ks * 8 + t4] : 0.f);
            u32 a2 = tf32c(vg ? xbase[(size_t)rg * DD + ks * 8 + t4 + 4] : 0.f);
            u32 a3 = tf32c(vg8 ? xbase[(size_t)rg8 * DD + ks * 8 + t4 + 4] : 0.f);
            int wr0 = (ks * 8 + t4) * 72;
            int wr1 = (ks * 8 + t4 + 4) * 72;
#pragma unroll
            for (int nb = 0; nb < 8; nb++) {
                u32 b0 = sW1u[wr0 + nb * 8 + g];
                u32 b1r = sW1u[wr1 + nb * 8 + g];
                mma8(C1[nb], a0, a1, a2, a3, b0, b1r);
            }
        }
#pragma unroll
        for (int nb = 0; nb < 8; nb++) {
            float h0 = C1[nb].x, h1 = C1[nb].y, h2 = C1[nb].z, h3 = C1[nb].w;
            h0 = 0.5f * h0 * (1.f + erff(h0 * 0.70710678118654752440f));
            h1 = 0.5f * h1 * (1.f + erff(h1 * 0.70710678118654752440f));
            h2 = 0.5f * h2 * (1.f + erff(h2 * 0.70710678118654752440f));
            h3 = 0.5f * h3 * (1.f + erff(h3 * 0.70710678118654752440f));
            int col = nb * 8 + 2 * t4;
            *(uint2*)&sHu[(w * 16 + g) * 72 + col] = make_uint2(tf32c(h0), tf32c(h1));
            *(uint2*)&sHu[(w * 16 + g + 8) * 72 + col] = make_uint2(tf32c(h2), tf32c(h3));
        }
        __syncwarp();
#pragma unroll
        for (int ks = 0; ks < 8; ks++) {
            u32 a0 = sHu[(w * 16 + g) * 72 + ks * 8 + t4];
            u32 a1 = sHu[(w * 16 + g + 8) * 72 + ks * 8 + t4];
            u32 a2 = sHu[(w * 16 + g) * 72 + ks * 8 + t4 + 4];
            u32 a3 = sHu[(w * 16 + g + 8) * 72 + ks * 8 + t4 + 4];
            int wr0 = (ks * 8 + t4) * 72;
            int wr1 = (ks * 8 + t4 + 4) * 72;
#pragma unroll
            for (int nb = 0; nb < 8; nb++) {
                u32 b0 = sW2u[wr0 + nb * 8 + g];
                u32 b1r = sW2u[wr1 + nb * 8 + g];
                mma8(C2[nb], a0, a1, a2, a3, b0, b1r);
            }
        }
    }

#pragma unroll 1
    for (int rp = 0; rp < 2; rp++) {
        int r = rp ? rg8 : rg;
        bool vr = rp ? vg8 : vg;
        float vx[8], vy[8];
#pragma unroll
        for (int nb = 0; nb < 8; nb++) {
            int col = nb * 8 + 2 * t4;
            float2 xv = vr ? *(const float2*)&xbase[(size_t)r * DD + col]
                           : make_float2(0.f, 0.f);
            float cva = rp ? C2[nb].z : C2[nb].x;
            float cvb = rp ? C2[nb].w : C2[nb].y;
            vx[nb] = cva + sB2[col] + xv.x;
            vy[nb] = cvb + sB2[col + 1] + xv.y;
        }
        float s = 0.f;
#pragma unroll
        for (int nb = 0; nb < 8; nb++) s += vx[nb] + vy[nb];
        s += __shfl_xor_sync(0xffffffffu, s, 1);
        s += __shfl_xor_sync(0xffffffffu, s, 2);
        float m = s * (1.f / DD);
        float q = 0.f;
#pragma unroll
        for (int nb = 0; nb < 8; nb++) {
            float d0 = vx[nb] - m, d1 = vy[nb] - m;
            q += d0 * d0 + d1 * d1;
        }
        q += __shfl_xor_sync(0xffffffffu, q, 1);
        q += __shfl_xor_sync(0xffffffffu, q, 2);
        float inv = rsqrtf(q * (1.f / DD) + 1e-5f);
        if (vr) {
            float* op = xout + ((size_t)b * NN + r) * DD;
#pragma unroll
            for (int nb = 0; nb < 8; nb++) {
                int col = nb * 8 + 2 * t4;
                float2 o2;
                o2.x = (vx[nb] - m) * inv * sG[col] + sBe[col];
                o2.y = (vy[nb] - m) * inv * sG[col + 1] + sBe[col + 1];
                *(float2*)&op[col] = o2;
            }
        }
    }
}

// ---------------------------------------------------------------------------
extern "C" void kernel_launch(void* const* d_in, const int* in_sizes, int n_in,
                              void* d_out, int out_size) {
    const float* expr = (const float*)d_in[0];
    const float* emb = (const float*)d_in[1];
    const float* Wq = (const float*)d_in[2];
    const float* Wk = (const float*)d_in[3];
    const float* Wv = (const float*)d_in[4];
    const float* projK = (const float*)d_in[5];
    const float* projV = (const float*)d_in[6];
    const float* Wo = (const float*)d_in[7];
    const float* bo = (const float*)d_in[8];
    const float* g1 = (const float*)d_in[9];
    const float* be1 = (const float*)d_in[10];
    const float* W1 = (const float*)d_in[11];
    const float* bf1 = (const float*)d_in[12];
    const float* W2 = (const float*)d_in[13];
    const float* bf2 = (const float*)d_in[14];
    const float* g2 = (const float*)d_in[15];
    const float* be2 = (const float*)d_in[16];
    float* out = (float*)d_out;

    void* xaddr = nullptr;
    cudaGetSymbolAddress(&xaddr, g_x);
    float* gx = (float*)xaddr;

    cudaFuncSetAttribute(attn_mma_kernel, cudaFuncAttributeMaxDynamicSharedMemorySize,
                         ATTN_SMEM_BYTES);
    cudaFuncSetAttribute(ffn_mma_kernel, cudaFuncAttributeMaxDynamicSharedMemorySize,
                         FFN_SMEM_BYTES);

    embed_kernel<<<(BB * NN + 255) / 256, 256>>>(expr, emb);

    for (int l = 0; l < LLAYERS; l++) {
        proj_mma_kernel<<<dim3(NSPLIT, BB, 2), 256>>>(projK + (size_t)l * NN * KK,
                                                      projV + (size_t)l * NN * KK);
        reduce_kernel<<<(2 * BB * KK * DD) / 256, 256>>>();
        kvproj_kernel<<<dim3(KK / 4, BB, 2), 256>>>(Wk + l * DD * DD,
                                                    Wv + l * DD * DD);
        attn_mma_kernel<<<dim3(ATILES, BB), 256, ATTN_SMEM_BYTES>>>(
            Wq + l * DD * DD, Wo + l * DD * DD, bo + l * DD, g1 + l * DD,
            be1 + l * DD);
        ffn_mma_kernel<<<dim3(ATILES, BB), 256, FFN_SMEM_BYTES>>>(
            W1 + (size_t)l * DD * FF, bf1 + l * FF, W2 + (size_t)l * FF * DD,
            bf2 + l * DD, g2 + l * DD, be2 + l * DD,
            (l == LLAYERS - 1) ? out : gx);
    }
}